// round 8
// baseline (speedup 1.0000x reference)
#include <cuda_runtime.h>
#include <cstdint>

// Problem constants
#define BB      128
#define TOPK    32
#define MN      64
#define NODES   258        // MAX_NODES + 2
#define HDIM    128
#define G3      384        // 3*H

// ---------------------------------------------------------------------------
// Device scratch
// ---------------------------------------------------------------------------
__device__ float    g_gi_rel[400 * 512];        // [rel][ch][4] gate-interleaved
__device__ float    g_gi_ent[BB * TOPK * G3];
__device__ uint16_t g_gh16 [BB * NODES * G3];   // gh in bf16

// ---------------------------------------------------------------------------
// Helpers
// ---------------------------------------------------------------------------
__device__ __forceinline__ float tanh_ap(float x) {
    float y; asm("tanh.approx.f32 %0, %1;" : "=f"(y) : "f"(x)); return y;
}
__device__ __forceinline__ float sigmoid_t(float x) {
    return fmaf(0.5f, tanh_ap(0.5f * x), 0.5f);
}
__device__ __forceinline__ uint32_t f2bf2(float lo, float hi) {
    uint32_t r;
    asm("cvt.rn.bf16x2.f32 %0, %1, %2;" : "=r"(r) : "f"(hi), "f"(lo));
    return r;
}
__device__ __forceinline__ void mma_bf16(float* d, const uint32_t* a, const uint32_t* b) {
    asm volatile(
        "mma.sync.aligned.m16n8k16.row.col.f32.bf16.bf16.f32 "
        "{%0,%1,%2,%3}, {%4,%5,%6,%7}, {%8,%9}, {%0,%1,%2,%3};"
        : "+f"(d[0]), "+f"(d[1]), "+f"(d[2]), "+f"(d[3])
        : "r"(a[0]), "r"(a[1]), "r"(a[2]), "r"(a[3]), "r"(b[0]), "r"(b[1]));
}

// ---------------------------------------------------------------------------
// Kernel 1: fused bf16 mma.sync GEMM (882 CTAs, routed by blockIdx.x)
// ---------------------------------------------------------------------------
#define APITCH 68
#define OFFA    0
#define OFFB    (128 * APITCH * 4)
#define OFFBIAS (OFFB + 128 * APITCH * 4)
#define OFFRIDX (OFFBIAS + 128 * 4)
#define GEMM_SMEM (OFFRIDX + 128 * 4)

__global__ __launch_bounds__(256, 2) void gemm_mma_kernel(
    const float* __restrict__ node_emb,
    const float* __restrict__ ent_tab,
    const float* __restrict__ rel_tab,
    const float* __restrict__ W_ih,
    const float* __restrict__ W_hh,
    const float* __restrict__ b_ih,
    const float* __restrict__ b_hh,
    const int*   __restrict__ aim_ent,
    uint16_t* __restrict__ out_gh,
    float* __restrict__ out_gi_ent,
    float* __restrict__ out_gi_rel)
{
    extern __shared__ char sm[];
    uint32_t* As = reinterpret_cast<uint32_t*>(sm + OFFA);
    uint32_t* Bs = reinterpret_cast<uint32_t*>(sm + OFFB);
    float*    sh_bias = reinterpret_cast<float*>(sm + OFFBIAS);
    int*      sh_ridx = reinterpret_cast<int*>(sm + OFFRIDX);

    const int tid  = threadIdx.x;
    const int wid  = tid >> 5;
    const int lane = tid & 31;

    int bx = blockIdx.x;
    const float* A; const int* gather = nullptr; int nrows;
    const float* W; int ldw, woff; const float* bias; float* outf = nullptr;
    int tile, gate, obf = 0, orel = 0;
    if (bx < 774) {
        tile = bx / 3; gate = bx % 3;
        A = node_emb; nrows = BB * NODES;
        W = W_hh; ldw = 128; woff = 0; bias = b_hh; obf = 1;
    } else if (bx < 870) {
        int i = bx - 774; tile = i / 3; gate = i % 3;
        A = ent_tab; gather = aim_ent; nrows = BB * TOPK;
        W = W_ih; ldw = 256; woff = 0; bias = b_ih; outf = out_gi_ent;
    } else {
        int i = bx - 870; tile = i / 3; gate = i % 3;
        A = rel_tab; nrows = 400;
        W = W_ih; ldw = 256; woff = 128; bias = nullptr;
        outf = out_gi_rel; orel = 1;
    }
    const int row0 = tile * 128;

    if (tid < 128) {
        int r = row0 + tid;
        sh_ridx[tid] = (r < nrows) ? (gather ? gather[r] : r) : -1;
        sh_bias[tid] = bias ? bias[gate * 128 + tid] : 0.0f;
    }
    __syncthreads();

    for (int idx = tid; idx < 128 * 32; idx += 256) {
        int i  = idx >> 5;
        int k4 = (idx & 31) << 2;
        int ridx = sh_ridx[i];
        float4 v = make_float4(0.f, 0.f, 0.f, 0.f);
        if (ridx >= 0)
            v = *reinterpret_cast<const float4*>(&A[(size_t)ridx * 128 + k4]);
        uint2 w = make_uint2(f2bf2(v.x, v.y), f2bf2(v.z, v.w));
        *reinterpret_cast<uint2*>(&As[i * APITCH + (k4 >> 1)]) = w;
    }
    for (int idx = tid; idx < 128 * 32; idx += 256) {
        int n  = idx >> 5;
        int k4 = (idx & 31) << 2;
        float4 v = *reinterpret_cast<const float4*>(&W[(size_t)(gate * 128 + n) * ldw + woff + k4]);
        uint2 w = make_uint2(f2bf2(v.x, v.y), f2bf2(v.z, v.w));
        *reinterpret_cast<uint2*>(&Bs[n * APITCH + (k4 >> 1)]) = w;
    }
    __syncthreads();

    const int quad  = lane >> 2;
    const int tq    = lane & 3;
    const int rbase = (wid >> 2) * 64;
    const int cbase = (wid & 3) * 32;

    float acc[4][4][4];
#pragma unroll
    for (int mt = 0; mt < 4; mt++)
#pragma unroll
        for (int nt = 0; nt < 4; nt++)
#pragma unroll
            for (int r = 0; r < 4; r++) acc[mt][nt][r] = 0.f;

#pragma unroll
    for (int ks = 0; ks < 8; ks++) {
        const int k0 = ks * 8;
        uint32_t af[4][4];
#pragma unroll
        for (int mt = 0; mt < 4; mt++) {
            int r = rbase + mt * 16 + quad;
            af[mt][0] = As[r * APITCH + k0 + tq];
            af[mt][1] = As[(r + 8) * APITCH + k0 + tq];
            af[mt][2] = As[r * APITCH + k0 + tq + 4];
            af[mt][3] = As[(r + 8) * APITCH + k0 + tq + 4];
        }
        uint32_t bf[4][2];
#pragma unroll
        for (int nt = 0; nt < 4; nt++) {
            int c = cbase + nt * 8 + quad;
            bf[nt][0] = Bs[c * APITCH + k0 + tq];
            bf[nt][1] = Bs[c * APITCH + k0 + tq + 4];
        }
#pragma unroll
        for (int mt = 0; mt < 4; mt++)
#pragma unroll
            for (int nt = 0; nt < 4; nt++)
                mma_bf16(acc[mt][nt], af[mt], bf[nt]);
    }

#pragma unroll
    for (int mt = 0; mt < 4; mt++) {
#pragma unroll
        for (int nt = 0; nt < 4; nt++) {
            const int col = cbase + nt * 8 + tq * 2;
            const float b0 = sh_bias[col], b1 = sh_bias[col + 1];
            const int r1 = row0 + rbase + mt * 16 + quad;
            const int r2 = r1 + 8;
            if (obf) {
                if (r1 < nrows)
                    *reinterpret_cast<uint32_t*>(
                        &out_gh[(size_t)r1 * G3 + gate * 128 + col]) =
                        f2bf2(acc[mt][nt][0] + b0, acc[mt][nt][1] + b1);
                if (r2 < nrows)
                    *reinterpret_cast<uint32_t*>(
                        &out_gh[(size_t)r2 * G3 + gate * 128 + col]) =
                        f2bf2(acc[mt][nt][2] + b0, acc[mt][nt][3] + b1);
            } else if (orel) {
                // gate-interleaved: [rel][ch][4]
                if (r1 < nrows) {
                    outf[(size_t)r1 * 512 + col * 4 + gate]       = acc[mt][nt][0] + b0;
                    outf[(size_t)r1 * 512 + (col + 1) * 4 + gate] = acc[mt][nt][1] + b1;
                }
                if (r2 < nrows) {
                    outf[(size_t)r2 * 512 + col * 4 + gate]       = acc[mt][nt][2] + b0;
                    outf[(size_t)r2 * 512 + (col + 1) * 4 + gate] = acc[mt][nt][3] + b1;
                }
            } else {
                if (r1 < nrows)
                    *reinterpret_cast<float2*>(&outf[(size_t)r1 * G3 + gate * 128 + col]) =
                        make_float2(acc[mt][nt][0] + b0, acc[mt][nt][1] + b1);
                if (r2 < nrows)
                    *reinterpret_cast<float2*>(&outf[(size_t)r2 * G3 + gate * 128 + col]) =
                        make_float2(acc[mt][nt][2] + b0, acc[mt][nt][3] + b1);
            }
        }
    }
}

// ---------------------------------------------------------------------------
// Kernel 2: GRU aggregation, worklist-balanced, 3 CTAs/SM.
// gh staged split: packed (r,z) u32 + n u16; h read from global (L2).
// ---------------------------------------------------------------------------
#define OFF_GRZ  0                               // u32 [258*32]   = 33024
#define OFF_GN   33024                           // u16 [258*32]   = 16512
#define OFF_GI   (OFF_GN + 16512)                // f32 [32*96]    = 12288
#define OFF_WORK (OFF_GI + 12288)                // i32 [2048]     =  8192
#define OFF_ACC  (OFF_WORK + 8192)               // f32 [32*32]    =  4096
#define OFF_PREF (OFF_ACC + 4096)                // i32 [33] pad 144
#define OFF_NUM  (OFF_PREF + 144)                // i32 [32]
#define OFF_AIM  (OFF_NUM + 128)                 // i32 [32]
#define AGG_SMEM (OFF_AIM + 128)                 // 74512 B

__global__ __launch_bounds__(512, 3) void aggregate_kernel(
    const float*    __restrict__ node_emb,
    const float*    __restrict__ gi_rel4,
    const float*    __restrict__ gi_ent,
    const uint16_t* __restrict__ gh_all,
    const int2*     __restrict__ neighbors,
    const int*      __restrict__ nb_num,
    const int*      __restrict__ aim_nodes,
    float* __restrict__ out)
{
    extern __shared__ char smraw[];
    uint32_t* sh_grz  = reinterpret_cast<uint32_t*>(smraw + OFF_GRZ);
    uint16_t* sh_gn   = reinterpret_cast<uint16_t*>(smraw + OFF_GN);
    float*    sh_gi   = reinterpret_cast<float*>(smraw + OFF_GI);
    int*      sh_work = reinterpret_cast<int*>(smraw + OFF_WORK);
    float*    sh_acc  = reinterpret_cast<float*>(smraw + OFF_ACC);
    int*      sh_pref = reinterpret_cast<int*>(smraw + OFF_PREF);
    int*      sh_num  = reinterpret_cast<int*>(smraw + OFF_NUM);
    int*      sh_aim  = reinterpret_cast<int*>(smraw + OFF_AIM);

    const int tid = threadIdx.x;
    const int c   = blockIdx.x;
    const int b   = blockIdx.y;
    const int cc0 = c * 32;

    // ---- fill: gh split (r,z) packed + n ----
    for (int idx = tid; idx < 258 * 4; idx += 512) {
        int n  = idx >> 2;
        int k8 = (idx & 3) * 8;
        const uint16_t* base = &gh_all[((size_t)b * NODES + n) * G3 + cc0 + k8];
        uint4 rv = *reinterpret_cast<const uint4*>(base);
        uint4 zv = *reinterpret_cast<const uint4*>(base + 128);
        uint4 nv = *reinterpret_cast<const uint4*>(base + 256);
        uint32_t* rz = &sh_grz[n * 32 + k8];
        *reinterpret_cast<uint4*>(rz) = make_uint4(
            __byte_perm(rv.x, zv.x, 0x5410), __byte_perm(rv.x, zv.x, 0x7632),
            __byte_perm(rv.y, zv.y, 0x5410), __byte_perm(rv.y, zv.y, 0x7632));
        *reinterpret_cast<uint4*>(rz + 4) = make_uint4(
            __byte_perm(rv.z, zv.z, 0x5410), __byte_perm(rv.z, zv.z, 0x7632),
            __byte_perm(rv.w, zv.w, 0x5410), __byte_perm(rv.w, zv.w, 0x7632));
        *reinterpret_cast<uint4*>(&sh_gn[n * 32 + k8]) = nv;
    }
    // base copy node_emb -> out (also warms cache for in-loop h loads)
    for (int idx = tid; idx < 258 * 8; idx += 512) {
        int n = idx >> 3, jj = (idx & 7) * 4;
        float4 v = *reinterpret_cast<const float4*>(
            &node_emb[((size_t)b * NODES + n) * HDIM + cc0 + jj]);
        *reinterpret_cast<float4*>(&out[((size_t)b * NODES + n) * HDIM + cc0 + jj]) = v;
    }
    for (int idx = tid; idx < 32 * 24; idx += 512) {
        int t = idx / 24, q = idx % 24;
        int gate = q >> 3, jj = (q & 7) * 4;
        float4 v = *reinterpret_cast<const float4*>(
            &gi_ent[((size_t)b * TOPK + t) * G3 + gate * 128 + cc0 + jj]);
        *reinterpret_cast<float4*>(&sh_gi[(t * 3 + gate) * 32 + jj]) = v;
    }
    for (int idx = tid; idx < 1024; idx += 512)
        sh_acc[idx] = 0.0f;
    if (tid < 32)
        sh_num[tid] = nb_num[b * TOPK + tid];
    if (tid >= 32 && tid < 64) {
        int t = tid - 32;
        int node = aim_nodes[b * TOPK + t];
        unsigned grp = __match_any_sync(0xFFFFFFFFu, node);
        int winner = (31 - __clz(grp)) == t;
        sh_aim[t] = winner ? node : -1;
    }
    __syncthreads();

    // ---- prefix scan over num (warp 0) ----
    if (tid < 32) {
        int s = sh_num[tid];
#pragma unroll
        for (int o = 1; o < 32; o <<= 1) {
            int x = __shfl_up_sync(0xFFFFFFFFu, s, o);
            if (tid >= o) s += x;
        }
        sh_pref[tid + 1] = s;
        if (tid == 0) sh_pref[0] = 0;
    }
    __syncthreads();

    const int V = sh_pref[32];

    // ---- worklist build: packed (t | node<<5 | rel<<15) ----
    for (int idx = tid; idx < TOPK * MN; idx += 512) {
        int t = idx >> 6, m = idx & 63;
        if (m < sh_num[t]) {
            int2 nb = neighbors[(size_t)b * TOPK * MN + idx];
            sh_work[sh_pref[t] + m] = t | (nb.x << 5) | (nb.y << 15);
        }
    }
    __syncthreads();

    // ---- balanced compute ----
    const int warp = tid >> 5;
    const int lane = tid & 31;
    const int vbeg = (V * warp) >> 4;
    const int vend = (V * (warp + 1)) >> 4;

    const float* base_g = gi_rel4 + (cc0 + lane) * 4;
    const float* base_h = node_emb + (size_t)b * NODES * HDIM + cc0 + lane;

    int   cur_t = -1;
    float gir = 0.f, giz = 0.f, gin = 0.f, acc = 0.f;

    for (int v0 = vbeg; v0 < vend; v0 += 4) {
        const int cnt = min(4, vend - v0);
        int w[4]; float g0[4], g1[4], g2[4], hh[4];
        uint32_t rz[4], gn[4];
#pragma unroll
        for (int j = 0; j < 4; j++) {
            if (j < cnt) {
                w[j] = sh_work[v0 + j];
                int nd  = (w[j] >> 5) & 1023;
                int rel = w[j] >> 15;
                const float* gp = base_g + rel * 512;
                float2 g01 = *reinterpret_cast<const float2*>(gp);
                g0[j] = g01.x; g1[j] = g01.y; g2[j] = __ldg(gp + 2);
                hh[j] = __ldg(base_h + nd * HDIM);
                rz[j] = sh_grz[nd * 32 + lane];
                gn[j] = sh_gn[nd * 32 + lane];
            }
        }
#pragma unroll
        for (int j = 0; j < 4; j++) {
            if (j < cnt) {
                int t = w[j] & 31;
                if (t != cur_t) {               // warp-uniform
                    if (cur_t >= 0) atomicAdd(&sh_acc[cur_t * 32 + lane], acc);
                    acc = 0.f;
                    cur_t = t;
                    gir = sh_gi[(t * 3 + 0) * 32 + lane];
                    giz = sh_gi[(t * 3 + 1) * 32 + lane];
                    gin = sh_gi[(t * 3 + 2) * 32 + lane];
                }
                float ghr = __uint_as_float(rz[j] << 16);
                float ghz = __uint_as_float(rz[j] & 0xFFFF0000u);
                float ghn = __uint_as_float(gn[j] << 16);
                float r = sigmoid_t(gir + g0[j] + ghr);
                float z = sigmoid_t(giz + g1[j] + ghz);
                float n = tanh_ap(fmaf(r, ghn, gin + g2[j]));
                acc += fmaf(z, hh[j] - n, n);
            }
        }
    }
    if (cur_t >= 0) atomicAdd(&sh_acc[cur_t * 32 + lane], acc);
    __syncthreads();

    // ---- epilogue: mean + scatter winners ----
    for (int t = warp; t < TOPK; t += 16) {
        const int aim = sh_aim[t];
        if (aim >= 0) {
            const int num = sh_num[t];
            float u = (num > 0) ? sh_acc[t * 32 + lane] / (float)num : 0.f;
            out[((size_t)b * NODES + aim) * HDIM + cc0 + lane] = u;
        }
    }
}

// ---------------------------------------------------------------------------
// Host launcher
// ---------------------------------------------------------------------------
extern "C" void kernel_launch(void* const* d_in, const int* in_sizes, int n_in,
                              void* d_out, int out_size)
{
    const float* node_emb = (const float*)d_in[0];
    const float* ent_tab  = (const float*)d_in[1];
    const float* rel_tab  = (const float*)d_in[2];
    const float* W_ih     = (const float*)d_in[3];
    const float* W_hh     = (const float*)d_in[4];
    const float* b_ih     = (const float*)d_in[5];
    const float* b_hh     = (const float*)d_in[6];
    const int*   aim_nd   = (const int*)d_in[7];
    const int*   aim_ent  = (const int*)d_in[8];
    const int*   nbrs     = (const int*)d_in[9];
    const int*   nb_num   = (const int*)d_in[10];
    float* out = (float*)d_out;

    float *p_gi_rel, *p_gi_ent; uint16_t* p_gh;
    cudaGetSymbolAddress((void**)&p_gi_rel, g_gi_rel);
    cudaGetSymbolAddress((void**)&p_gi_ent, g_gi_ent);
    cudaGetSymbolAddress((void**)&p_gh,     g_gh16);

    cudaFuncSetAttribute(gemm_mma_kernel,
        cudaFuncAttributeMaxDynamicSharedMemorySize, GEMM_SMEM);
    cudaFuncSetAttribute(aggregate_kernel,
        cudaFuncAttributeMaxDynamicSharedMemorySize, AGG_SMEM);

    // 1) fused GEMMs (bf16 tensor cores)
    gemm_mma_kernel<<<882, 256, GEMM_SMEM>>>(
        node_emb, ent_tab, rel_tab, W_ih, W_hh, b_ih, b_hh, aim_ent,
        p_gh, p_gi_ent, p_gi_rel);

    // 2) GRU + masked mean + fused base-copy/dupmask/scatter (3 CTAs/SM)
    aggregate_kernel<<<dim3(4, BB), 512, AGG_SMEM>>>(
        node_emb, p_gi_rel, p_gi_ent, p_gh,
        (const int2*)nbrs, nb_num, aim_nd, out);
}

// round 9
// speedup vs baseline: 1.2262x; 1.2262x over previous
#include <cuda_runtime.h>
#include <cstdint>

// Problem constants
#define BB      128
#define TOPK    32
#define MN      64
#define NODES   258        // MAX_NODES + 2
#define HDIM    128
#define G3      384        // 3*H

// ---------------------------------------------------------------------------
// Device scratch
// ---------------------------------------------------------------------------
__device__ uint16_t g_gi_rel16[400 * 512];      // bf16 [rel][ch][4]: r,z,n,pad
__device__ float    g_gi_ent[BB * TOPK * G3];
__device__ uint16_t g_gh16 [BB * NODES * G3];   // gh in bf16

// ---------------------------------------------------------------------------
// Helpers
// ---------------------------------------------------------------------------
__device__ __forceinline__ float tanh_ap(float x) {
    float y; asm("tanh.approx.f32 %0, %1;" : "=f"(y) : "f"(x)); return y;
}
__device__ __forceinline__ float sigmoid_t(float x) {
    return fmaf(0.5f, tanh_ap(0.5f * x), 0.5f);
}
__device__ __forceinline__ float bf2f(uint16_t u) {
    return __uint_as_float(((uint32_t)u) << 16);
}
__device__ __forceinline__ uint32_t f2bf2(float lo, float hi) {
    uint32_t r;
    asm("cvt.rn.bf16x2.f32 %0, %1, %2;" : "=r"(r) : "f"(hi), "f"(lo));
    return r;
}
__device__ __forceinline__ uint16_t f2bf1(float x) {
    return (uint16_t)(f2bf2(x, x) & 0xFFFFu);
}
__device__ __forceinline__ void mma_bf16(float* d, const uint32_t* a, const uint32_t* b) {
    asm volatile(
        "mma.sync.aligned.m16n8k16.row.col.f32.bf16.bf16.f32 "
        "{%0,%1,%2,%3}, {%4,%5,%6,%7}, {%8,%9}, {%0,%1,%2,%3};"
        : "+f"(d[0]), "+f"(d[1]), "+f"(d[2]), "+f"(d[3])
        : "r"(a[0]), "r"(a[1]), "r"(a[2]), "r"(a[3]), "r"(b[0]), "r"(b[1]));
}

// ---------------------------------------------------------------------------
// Kernel 1: fused bf16 mma.sync GEMM (882 CTAs, routed by blockIdx.x)
// ---------------------------------------------------------------------------
#define APITCH 68
#define OFFA    0
#define OFFB    (128 * APITCH * 4)
#define OFFBIAS (OFFB + 128 * APITCH * 4)
#define OFFRIDX (OFFBIAS + 128 * 4)
#define GEMM_SMEM (OFFRIDX + 128 * 4)

__global__ __launch_bounds__(256, 2) void gemm_mma_kernel(
    const float* __restrict__ node_emb,
    const float* __restrict__ ent_tab,
    const float* __restrict__ rel_tab,
    const float* __restrict__ W_ih,
    const float* __restrict__ W_hh,
    const float* __restrict__ b_ih,
    const float* __restrict__ b_hh,
    const int*   __restrict__ aim_ent,
    uint16_t* __restrict__ out_gh,
    float* __restrict__ out_gi_ent,
    uint16_t* __restrict__ out_gi_rel)
{
    extern __shared__ char sm[];
    uint32_t* As = reinterpret_cast<uint32_t*>(sm + OFFA);
    uint32_t* Bs = reinterpret_cast<uint32_t*>(sm + OFFB);
    float*    sh_bias = reinterpret_cast<float*>(sm + OFFBIAS);
    int*      sh_ridx = reinterpret_cast<int*>(sm + OFFRIDX);

    const int tid  = threadIdx.x;
    const int wid  = tid >> 5;
    const int lane = tid & 31;

    int bx = blockIdx.x;
    const float* A; const int* gather = nullptr; int nrows;
    const float* W; int ldw, woff; const float* bias; float* outf = nullptr;
    int tile, gate, obf = 0, orel = 0;
    if (bx < 774) {
        tile = bx / 3; gate = bx % 3;
        A = node_emb; nrows = BB * NODES;
        W = W_hh; ldw = 128; woff = 0; bias = b_hh; obf = 1;
    } else if (bx < 870) {
        int i = bx - 774; tile = i / 3; gate = i % 3;
        A = ent_tab; gather = aim_ent; nrows = BB * TOPK;
        W = W_ih; ldw = 256; woff = 0; bias = b_ih; outf = out_gi_ent;
    } else {
        int i = bx - 870; tile = i / 3; gate = i % 3;
        A = rel_tab; nrows = 400;
        W = W_ih; ldw = 256; woff = 128; bias = nullptr; orel = 1;
    }
    const int row0 = tile * 128;

    if (tid < 128) {
        int r = row0 + tid;
        sh_ridx[tid] = (r < nrows) ? (gather ? gather[r] : r) : -1;
        sh_bias[tid] = bias ? bias[gate * 128 + tid] : 0.0f;
    }
    __syncthreads();

    for (int idx = tid; idx < 128 * 32; idx += 256) {
        int i  = idx >> 5;
        int k4 = (idx & 31) << 2;
        int ridx = sh_ridx[i];
        float4 v = make_float4(0.f, 0.f, 0.f, 0.f);
        if (ridx >= 0)
            v = *reinterpret_cast<const float4*>(&A[(size_t)ridx * 128 + k4]);
        uint2 w = make_uint2(f2bf2(v.x, v.y), f2bf2(v.z, v.w));
        *reinterpret_cast<uint2*>(&As[i * APITCH + (k4 >> 1)]) = w;
    }
    for (int idx = tid; idx < 128 * 32; idx += 256) {
        int n  = idx >> 5;
        int k4 = (idx & 31) << 2;
        float4 v = *reinterpret_cast<const float4*>(&W[(size_t)(gate * 128 + n) * ldw + woff + k4]);
        uint2 w = make_uint2(f2bf2(v.x, v.y), f2bf2(v.z, v.w));
        *reinterpret_cast<uint2*>(&Bs[n * APITCH + (k4 >> 1)]) = w;
    }
    __syncthreads();

    const int quad  = lane >> 2;
    const int tq    = lane & 3;
    const int rbase = (wid >> 2) * 64;
    const int cbase = (wid & 3) * 32;

    float acc[4][4][4];
#pragma unroll
    for (int mt = 0; mt < 4; mt++)
#pragma unroll
        for (int nt = 0; nt < 4; nt++)
#pragma unroll
            for (int r = 0; r < 4; r++) acc[mt][nt][r] = 0.f;

#pragma unroll
    for (int ks = 0; ks < 8; ks++) {
        const int k0 = ks * 8;
        uint32_t af[4][4];
#pragma unroll
        for (int mt = 0; mt < 4; mt++) {
            int r = rbase + mt * 16 + quad;
            af[mt][0] = As[r * APITCH + k0 + tq];
            af[mt][1] = As[(r + 8) * APITCH + k0 + tq];
            af[mt][2] = As[r * APITCH + k0 + tq + 4];
            af[mt][3] = As[(r + 8) * APITCH + k0 + tq + 4];
        }
        uint32_t bf[4][2];
#pragma unroll
        for (int nt = 0; nt < 4; nt++) {
            int c = cbase + nt * 8 + quad;
            bf[nt][0] = Bs[c * APITCH + k0 + tq];
            bf[nt][1] = Bs[c * APITCH + k0 + tq + 4];
        }
#pragma unroll
        for (int mt = 0; mt < 4; mt++)
#pragma unroll
            for (int nt = 0; nt < 4; nt++)
                mma_bf16(acc[mt][nt], af[mt], bf[nt]);
    }

#pragma unroll
    for (int mt = 0; mt < 4; mt++) {
#pragma unroll
        for (int nt = 0; nt < 4; nt++) {
            const int col = cbase + nt * 8 + tq * 2;
            const float b0 = sh_bias[col], b1 = sh_bias[col + 1];
            const int r1 = row0 + rbase + mt * 16 + quad;
            const int r2 = r1 + 8;
            if (obf) {
                if (r1 < nrows)
                    *reinterpret_cast<uint32_t*>(
                        &out_gh[(size_t)r1 * G3 + gate * 128 + col]) =
                        f2bf2(acc[mt][nt][0] + b0, acc[mt][nt][1] + b1);
                if (r2 < nrows)
                    *reinterpret_cast<uint32_t*>(
                        &out_gh[(size_t)r2 * G3 + gate * 128 + col]) =
                        f2bf2(acc[mt][nt][2] + b0, acc[mt][nt][3] + b1);
            } else if (orel) {
                // bf16 gate-interleaved: [rel][ch][4] slots r,z,n,pad
                if (r1 < nrows) {
                    out_gi_rel[(size_t)r1 * 512 + col * 4 + gate]       = f2bf1(acc[mt][nt][0] + b0);
                    out_gi_rel[(size_t)r1 * 512 + (col + 1) * 4 + gate] = f2bf1(acc[mt][nt][1] + b1);
                }
                if (r2 < nrows) {
                    out_gi_rel[(size_t)r2 * 512 + col * 4 + gate]       = f2bf1(acc[mt][nt][2] + b0);
                    out_gi_rel[(size_t)r2 * 512 + (col + 1) * 4 + gate] = f2bf1(acc[mt][nt][3] + b1);
                }
            } else {
                if (r1 < nrows)
                    *reinterpret_cast<float2*>(&outf[(size_t)r1 * G3 + gate * 128 + col]) =
                        make_float2(acc[mt][nt][0] + b0, acc[mt][nt][1] + b1);
                if (r2 < nrows)
                    *reinterpret_cast<float2*>(&outf[(size_t)r2 * G3 + gate * 128 + col]) =
                        make_float2(acc[mt][nt][2] + b0, acc[mt][nt][3] + b1);
            }
        }
    }
}

// ---------------------------------------------------------------------------
// Kernel 2: GRU aggregation, worklist-balanced, 2 CTAs/SM (R7 structure),
// gi_rel via single LDG.64 (bf16 gate-interleaved).
// ---------------------------------------------------------------------------
#define OFF_GH   0                               // u16 [258*96]   = 49536
#define OFF_H    49536                           // f32 [258*32]   = 33024
#define OFF_GI   (OFF_H + 33024)                 // f32 [32*96]    = 12288
#define OFF_WORK (OFF_GI + 12288)                // i32 [2048]     =  8192
#define OFF_ACC  (OFF_WORK + 8192)               // f32 [32*32]    =  4096
#define OFF_PREF (OFF_ACC + 4096)                // i32 [33] pad 144
#define OFF_NUM  (OFF_PREF + 144)                // i32 [32]
#define OFF_AIM  (OFF_NUM + 128)                 // i32 [32]
#define AGG_SMEM (OFF_AIM + 128)                 // 107,536 B

__global__ __launch_bounds__(512, 2) void aggregate_kernel(
    const float*    __restrict__ node_emb,
    const uint16_t* __restrict__ gi_rel16,
    const float*    __restrict__ gi_ent,
    const uint16_t* __restrict__ gh_all,
    const int2*     __restrict__ neighbors,
    const int*      __restrict__ nb_num,
    const int*      __restrict__ aim_nodes,
    float* __restrict__ out)
{
    extern __shared__ char smraw[];
    uint16_t* sh_gh   = reinterpret_cast<uint16_t*>(smraw + OFF_GH);
    float*    sh_h    = reinterpret_cast<float*>(smraw + OFF_H);
    float*    sh_gi   = reinterpret_cast<float*>(smraw + OFF_GI);
    int*      sh_work = reinterpret_cast<int*>(smraw + OFF_WORK);
    float*    sh_acc  = reinterpret_cast<float*>(smraw + OFF_ACC);
    int*      sh_pref = reinterpret_cast<int*>(smraw + OFF_PREF);
    int*      sh_num  = reinterpret_cast<int*>(smraw + OFF_NUM);
    int*      sh_aim  = reinterpret_cast<int*>(smraw + OFF_AIM);

    const int tid = threadIdx.x;
    const int c   = blockIdx.x;
    const int b   = blockIdx.y;
    const int cc0 = c * 32;

    // ---- fill phase ----
    for (int idx = tid; idx < 258 * 12; idx += 512) {
        int n = idx / 12, q = idx % 12;
        int gate = q >> 2, j8 = (q & 3) * 8;
        uint4 v = *reinterpret_cast<const uint4*>(
            &gh_all[((size_t)b * NODES + n) * G3 + gate * 128 + cc0 + j8]);
        *reinterpret_cast<uint4*>(&sh_gh[(n * 3 + gate) * 32 + j8]) = v;
    }
    for (int idx = tid; idx < 258 * 8; idx += 512) {
        int n = idx >> 3, jj = (idx & 7) * 4;
        float4 v = *reinterpret_cast<const float4*>(
            &node_emb[((size_t)b * NODES + n) * HDIM + cc0 + jj]);
        *reinterpret_cast<float4*>(&sh_h[n * 32 + jj]) = v;
        *reinterpret_cast<float4*>(&out[((size_t)b * NODES + n) * HDIM + cc0 + jj]) = v;
    }
    for (int idx = tid; idx < 32 * 24; idx += 512) {
        int t = idx / 24, q = idx % 24;
        int gate = q >> 3, jj = (q & 7) * 4;
        float4 v = *reinterpret_cast<const float4*>(
            &gi_ent[((size_t)b * TOPK + t) * G3 + gate * 128 + cc0 + jj]);
        *reinterpret_cast<float4*>(&sh_gi[(t * 3 + gate) * 32 + jj]) = v;
    }
    for (int idx = tid; idx < 1024; idx += 512)
        sh_acc[idx] = 0.0f;
    if (tid < 32)
        sh_num[tid] = nb_num[b * TOPK + tid];
    if (tid >= 32 && tid < 64) {
        int t = tid - 32;
        int node = aim_nodes[b * TOPK + t];
        unsigned grp = __match_any_sync(0xFFFFFFFFu, node);
        int winner = (31 - __clz(grp)) == t;
        sh_aim[t] = winner ? node : -1;
    }
    __syncthreads();

    // ---- prefix scan over num (warp 0) ----
    if (tid < 32) {
        int s = sh_num[tid];
#pragma unroll
        for (int o = 1; o < 32; o <<= 1) {
            int x = __shfl_up_sync(0xFFFFFFFFu, s, o);
            if (tid >= o) s += x;
        }
        sh_pref[tid + 1] = s;
        if (tid == 0) sh_pref[0] = 0;
    }
    __syncthreads();

    const int V = sh_pref[32];

    // ---- worklist build: packed (t | node<<5 | rel<<15) ----
    for (int idx = tid; idx < TOPK * MN; idx += 512) {
        int t = idx >> 6, m = idx & 63;
        if (m < sh_num[t]) {
            int2 nb = neighbors[(size_t)b * TOPK * MN + idx];
            sh_work[sh_pref[t] + m] = t | (nb.x << 5) | (nb.y << 15);
        }
    }
    __syncthreads();

    // ---- balanced compute: warp w handles v in [V*w/16, V*(w+1)/16) ----
    const int warp = tid >> 5;
    const int lane = tid & 31;
    const int vbeg = (V * warp) >> 4;
    const int vend = (V * (warp + 1)) >> 4;

    const uint16_t* base_g = gi_rel16 + (cc0 + lane) * 4;

    int   cur_t = -1;
    float gir = 0.f, giz = 0.f, gin = 0.f, acc = 0.f;

    for (int v0 = vbeg; v0 < vend; v0 += 8) {
        const int cnt = min(8, vend - v0);
        int tt[8], nd[8]; uint2 gv[8];
#pragma unroll
        for (int j = 0; j < 8; j++) {
            if (j < cnt) {
                int w32 = sh_work[v0 + j];
                tt[j] = w32 & 31;
                nd[j] = (w32 >> 5) & 1023;
                int rel = w32 >> 15;
                gv[j] = __ldg(reinterpret_cast<const uint2*>(base_g + rel * 512));
            }
        }
#pragma unroll
        for (int j = 0; j < 8; j++) {
            if (j < cnt) {
                if (tt[j] != cur_t) {           // warp-uniform branch
                    if (cur_t >= 0) atomicAdd(&sh_acc[cur_t * 32 + lane], acc);
                    acc = 0.f;
                    cur_t = tt[j];
                    gir = sh_gi[(cur_t * 3 + 0) * 32 + lane];
                    giz = sh_gi[(cur_t * 3 + 1) * 32 + lane];
                    gin = sh_gi[(cur_t * 3 + 2) * 32 + lane];
                }
                const uint16_t* gh = sh_gh + nd[j] * 96 + lane;
                const float h  = sh_h[nd[j] * 32 + lane];
                float g0 = __uint_as_float(gv[j].x << 16);
                float g1 = __uint_as_float(gv[j].x & 0xFFFF0000u);
                float g2 = __uint_as_float(gv[j].y << 16);
                float r = sigmoid_t(gir + g0 + bf2f(gh[0]));
                float z = sigmoid_t(giz + g1 + bf2f(gh[32]));
                float n = tanh_ap(fmaf(r, bf2f(gh[64]), gin + g2));
                acc += fmaf(z, h - n, n);
            }
        }
    }
    if (cur_t >= 0) atomicAdd(&sh_acc[cur_t * 32 + lane], acc);
    __syncthreads();

    // ---- epilogue: mean + scatter winners ----
    for (int t = warp; t < TOPK; t += 16) {
        const int aim = sh_aim[t];
        if (aim >= 0) {
            const int num = sh_num[t];
            float u = (num > 0) ? sh_acc[t * 32 + lane] / (float)num : 0.f;
            out[((size_t)b * NODES + aim) * HDIM + cc0 + lane] = u;
        }
    }
}

// ---------------------------------------------------------------------------
// Host launcher
// ---------------------------------------------------------------------------
extern "C" void kernel_launch(void* const* d_in, const int* in_sizes, int n_in,
                              void* d_out, int out_size)
{
    const float* node_emb = (const float*)d_in[0];
    const float* ent_tab  = (const float*)d_in[1];
    const float* rel_tab  = (const float*)d_in[2];
    const float* W_ih     = (const float*)d_in[3];
    const float* W_hh     = (const float*)d_in[4];
    const float* b_ih     = (const float*)d_in[5];
    const float* b_hh     = (const float*)d_in[6];
    const int*   aim_nd   = (const int*)d_in[7];
    const int*   aim_ent  = (const int*)d_in[8];
    const int*   nbrs     = (const int*)d_in[9];
    const int*   nb_num   = (const int*)d_in[10];
    float* out = (float*)d_out;

    float* p_gi_ent; uint16_t *p_gi_rel, *p_gh;
    cudaGetSymbolAddress((void**)&p_gi_rel, g_gi_rel16);
    cudaGetSymbolAddress((void**)&p_gi_ent, g_gi_ent);
    cudaGetSymbolAddress((void**)&p_gh,     g_gh16);

    cudaFuncSetAttribute(gemm_mma_kernel,
        cudaFuncAttributeMaxDynamicSharedMemorySize, GEMM_SMEM);
    cudaFuncSetAttribute(aggregate_kernel,
        cudaFuncAttributeMaxDynamicSharedMemorySize, AGG_SMEM);

    // 1) fused GEMMs (bf16 tensor cores)
    gemm_mma_kernel<<<882, 256, GEMM_SMEM>>>(
        node_emb, ent_tab, rel_tab, W_ih, W_hh, b_ih, b_hh, aim_ent,
        p_gh, p_gi_ent, p_gi_rel);

    // 2) GRU + masked mean + fused base-copy/dupmask/scatter
    aggregate_kernel<<<dim3(4, BB), 512, AGG_SMEM>>>(
        node_emb, p_gi_rel, p_gi_ent, p_gh,
        (const int2*)nbrs, nb_num, aim_nd, out);
}

// round 10
// speedup vs baseline: 1.2961x; 1.0570x over previous
#include <cuda_runtime.h>
#include <cstdint>

// Problem constants
#define BB      128
#define TOPK    32
#define MN      64
#define NODES   258        // MAX_NODES + 2
#define HDIM    128
#define G3      384        // 3*H

// ---------------------------------------------------------------------------
// Device scratch
// ---------------------------------------------------------------------------
__device__ uint16_t g_gi_rel16[400 * 512];      // bf16 [rel][ch][4]: r,z,n,pad
__device__ float    g_gi_ent[BB * TOPK * G3];
__device__ uint16_t g_gh16 [BB * NODES * G3];   // gh in bf16

// ---------------------------------------------------------------------------
// Helpers
// ---------------------------------------------------------------------------
__device__ __forceinline__ float tanh_ap(float x) {
    float y; asm("tanh.approx.f32 %0, %1;" : "=f"(y) : "f"(x)); return y;
}
__device__ __forceinline__ float sigmoid_t(float x) {
    return fmaf(0.5f, tanh_ap(0.5f * x), 0.5f);
}
__device__ __forceinline__ uint32_t f2bf2(float lo, float hi) {
    uint32_t r;
    asm("cvt.rn.bf16x2.f32 %0, %1, %2;" : "=r"(r) : "f"(hi), "f"(lo));
    return r;
}
__device__ __forceinline__ uint16_t f2bf1(float x) {
    return (uint16_t)(f2bf2(x, x) & 0xFFFFu);
}
__device__ __forceinline__ void mma_bf16(float* d, const uint32_t* a, const uint32_t* b) {
    asm volatile(
        "mma.sync.aligned.m16n8k16.row.col.f32.bf16.bf16.f32 "
        "{%0,%1,%2,%3}, {%4,%5,%6,%7}, {%8,%9}, {%0,%1,%2,%3};"
        : "+f"(d[0]), "+f"(d[1]), "+f"(d[2]), "+f"(d[3])
        : "r"(a[0]), "r"(a[1]), "r"(a[2]), "r"(a[3]), "r"(b[0]), "r"(b[1]));
}

// ---------------------------------------------------------------------------
// Kernel 1: fused bf16 mma.sync GEMM, 294 CTAs (one wave @ 2 CTA/SM).
// Each CTA: one 128-row tile, ALL 3 gates (B reloaded per gate, A loaded once).
//   [0,258):   gh16   = bf16(node_emb @ W_hh^T + b_hh)
//   [258,290): gi_ent = ent_tab[aim_ent] @ W_ih[:,:128]^T + b_ih   (f32)
//   [290,294): gi_rel = bf16 gate-interleaved rel_tab @ W_ih[:,128:256]^T
// ---------------------------------------------------------------------------
#define APITCH 68
#define OFFA    0
#define OFFB    (128 * APITCH * 4)               // 34816
#define OFFBIAS (OFFB + 128 * APITCH * 4)        // 69632  (384 f)
#define OFFRIDX (OFFBIAS + 384 * 4)              // 71168  (128 i)
#define GEMM_SMEM (OFFRIDX + 128 * 4)            // 71680

__global__ __launch_bounds__(256, 2) void gemm_mma_kernel(
    const float* __restrict__ node_emb,
    const float* __restrict__ ent_tab,
    const float* __restrict__ rel_tab,
    const float* __restrict__ W_ih,
    const float* __restrict__ W_hh,
    const float* __restrict__ b_ih,
    const float* __restrict__ b_hh,
    const int*   __restrict__ aim_ent,
    uint16_t* __restrict__ out_gh,
    float* __restrict__ out_gi_ent,
    uint16_t* __restrict__ out_gi_rel)
{
    extern __shared__ char sm[];
    uint32_t* As = reinterpret_cast<uint32_t*>(sm + OFFA);
    uint32_t* Bs = reinterpret_cast<uint32_t*>(sm + OFFB);
    float*    sh_bias = reinterpret_cast<float*>(sm + OFFBIAS);
    int*      sh_ridx = reinterpret_cast<int*>(sm + OFFRIDX);

    const int tid  = threadIdx.x;
    const int wid  = tid >> 5;
    const int lane = tid & 31;

    int bx = blockIdx.x;
    const float* A; const int* gather = nullptr; int nrows;
    const float* W; int ldw, woff; const float* bias; float* outf = nullptr;
    int tile, obf = 0, orel = 0;
    if (bx < 258) {
        tile = bx;
        A = node_emb; nrows = BB * NODES;
        W = W_hh; ldw = 128; woff = 0; bias = b_hh; obf = 1;
    } else if (bx < 290) {
        tile = bx - 258;
        A = ent_tab; gather = aim_ent; nrows = BB * TOPK;
        W = W_ih; ldw = 256; woff = 0; bias = b_ih; outf = out_gi_ent;
    } else {
        tile = bx - 290;
        A = rel_tab; nrows = 400;
        W = W_ih; ldw = 256; woff = 128; bias = nullptr; orel = 1;
    }
    const int row0 = tile * 128;

    if (tid < 128) {
        int r = row0 + tid;
        sh_ridx[tid] = (r < nrows) ? (gather ? gather[r] : r) : -1;
    }
    for (int i = tid; i < G3; i += 256)
        sh_bias[i] = bias ? bias[i] : 0.0f;
    __syncthreads();

    // ---- fill A tile once (bf16 pairs) ----
    for (int idx = tid; idx < 128 * 32; idx += 256) {
        int i  = idx >> 5;
        int k4 = (idx & 31) << 2;
        int ridx = sh_ridx[i];
        float4 v = make_float4(0.f, 0.f, 0.f, 0.f);
        if (ridx >= 0)
            v = *reinterpret_cast<const float4*>(&A[(size_t)ridx * 128 + k4]);
        uint2 w = make_uint2(f2bf2(v.x, v.y), f2bf2(v.z, v.w));
        *reinterpret_cast<uint2*>(&As[i * APITCH + (k4 >> 1)]) = w;
    }

    const int quad  = lane >> 2;
    const int tq    = lane & 3;
    const int rbase = (wid >> 2) * 64;
    const int cbase = (wid & 3) * 32;

    for (int gate = 0; gate < 3; gate++) {
        // ---- fill B tile for this gate ----
        for (int idx = tid; idx < 128 * 32; idx += 256) {
            int n  = idx >> 5;
            int k4 = (idx & 31) << 2;
            float4 v = *reinterpret_cast<const float4*>(
                &W[(size_t)(gate * 128 + n) * ldw + woff + k4]);
            uint2 w = make_uint2(f2bf2(v.x, v.y), f2bf2(v.z, v.w));
            *reinterpret_cast<uint2*>(&Bs[n * APITCH + (k4 >> 1)]) = w;
        }
        __syncthreads();

        float acc[4][4][4];
#pragma unroll
        for (int mt = 0; mt < 4; mt++)
#pragma unroll
            for (int nt = 0; nt < 4; nt++)
#pragma unroll
                for (int r = 0; r < 4; r++) acc[mt][nt][r] = 0.f;

#pragma unroll
        for (int ks = 0; ks < 8; ks++) {
            const int k0 = ks * 8;
            uint32_t af[4][4];
#pragma unroll
            for (int mt = 0; mt < 4; mt++) {
                int r = rbase + mt * 16 + quad;
                af[mt][0] = As[r * APITCH + k0 + tq];
                af[mt][1] = As[(r + 8) * APITCH + k0 + tq];
                af[mt][2] = As[r * APITCH + k0 + tq + 4];
                af[mt][3] = As[(r + 8) * APITCH + k0 + tq + 4];
            }
            uint32_t bf[4][2];
#pragma unroll
            for (int nt = 0; nt < 4; nt++) {
                int c = cbase + nt * 8 + quad;
                bf[nt][0] = Bs[c * APITCH + k0 + tq];
                bf[nt][1] = Bs[c * APITCH + k0 + tq + 4];
            }
#pragma unroll
            for (int mt = 0; mt < 4; mt++)
#pragma unroll
                for (int nt = 0; nt < 4; nt++)
                    mma_bf16(acc[mt][nt], af[mt], bf[nt]);
        }

        // ---- epilogue for this gate ----
#pragma unroll
        for (int mt = 0; mt < 4; mt++) {
#pragma unroll
            for (int nt = 0; nt < 4; nt++) {
                const int col = cbase + nt * 8 + tq * 2;
                const float b0 = sh_bias[gate * 128 + col];
                const float b1 = sh_bias[gate * 128 + col + 1];
                const int r1 = row0 + rbase + mt * 16 + quad;
                const int r2 = r1 + 8;
                if (obf) {
                    if (r1 < nrows)
                        *reinterpret_cast<uint32_t*>(
                            &out_gh[(size_t)r1 * G3 + gate * 128 + col]) =
                            f2bf2(acc[mt][nt][0] + b0, acc[mt][nt][1] + b1);
                    if (r2 < nrows)
                        *reinterpret_cast<uint32_t*>(
                            &out_gh[(size_t)r2 * G3 + gate * 128 + col]) =
                            f2bf2(acc[mt][nt][2] + b0, acc[mt][nt][3] + b1);
                } else if (orel) {
                    if (r1 < nrows) {
                        out_gi_rel[(size_t)r1 * 512 + col * 4 + gate]       = f2bf1(acc[mt][nt][0] + b0);
                        out_gi_rel[(size_t)r1 * 512 + (col + 1) * 4 + gate] = f2bf1(acc[mt][nt][1] + b1);
                    }
                    if (r2 < nrows) {
                        out_gi_rel[(size_t)r2 * 512 + col * 4 + gate]       = f2bf1(acc[mt][nt][2] + b0);
                        out_gi_rel[(size_t)r2 * 512 + (col + 1) * 4 + gate] = f2bf1(acc[mt][nt][3] + b1);
                    }
                } else {
                    if (r1 < nrows)
                        *reinterpret_cast<float2*>(&outf[(size_t)r1 * G3 + gate * 128 + col]) =
                            make_float2(acc[mt][nt][0] + b0, acc[mt][nt][1] + b1);
                    if (r2 < nrows)
                        *reinterpret_cast<float2*>(&outf[(size_t)r2 * G3 + gate * 128 + col]) =
                            make_float2(acc[mt][nt][2] + b0, acc[mt][nt][3] + b1);
                }
            }
        }
        __syncthreads();   // B buffer reuse (WAR) guard
    }
}

// ---------------------------------------------------------------------------
// Kernel 2: GRU aggregation, worklist-balanced, 2 CTAs/SM.
// gh staged split: packed (r,z) u32 + n u16; h in smem (fp32);
// gi_rel via single LDG.64 (bf16 gate-interleaved).
// ---------------------------------------------------------------------------
#define OFF_GRZ  0                               // u32 [258*32]   = 33024
#define OFF_GN   33024                           // u16 [258*32]   = 16512
#define OFF_H    (OFF_GN + 16512)                // f32 [258*32]   = 33024
#define OFF_GI   (OFF_H + 33024)                 // f32 [32*96]    = 12288
#define OFF_WORK (OFF_GI + 12288)                // i32 [2048]     =  8192
#define OFF_ACC  (OFF_WORK + 8192)               // f32 [32*32]    =  4096
#define OFF_PREF (OFF_ACC + 4096)                // i32 [33] pad 144
#define OFF_NUM  (OFF_PREF + 144)                // i32 [32]
#define OFF_AIM  (OFF_NUM + 128)                 // i32 [32]
#define AGG_SMEM (OFF_AIM + 128)                 // 107,536 B

__global__ __launch_bounds__(512, 2) void aggregate_kernel(
    const float*    __restrict__ node_emb,
    const uint16_t* __restrict__ gi_rel16,
    const float*    __restrict__ gi_ent,
    const uint16_t* __restrict__ gh_all,
    const int2*     __restrict__ neighbors,
    const int*      __restrict__ nb_num,
    const int*      __restrict__ aim_nodes,
    float* __restrict__ out)
{
    extern __shared__ char smraw[];
    uint32_t* sh_grz  = reinterpret_cast<uint32_t*>(smraw + OFF_GRZ);
    uint16_t* sh_gn   = reinterpret_cast<uint16_t*>(smraw + OFF_GN);
    float*    sh_h    = reinterpret_cast<float*>(smraw + OFF_H);
    float*    sh_gi   = reinterpret_cast<float*>(smraw + OFF_GI);
    int*      sh_work = reinterpret_cast<int*>(smraw + OFF_WORK);
    float*    sh_acc  = reinterpret_cast<float*>(smraw + OFF_ACC);
    int*      sh_pref = reinterpret_cast<int*>(smraw + OFF_PREF);
    int*      sh_num  = reinterpret_cast<int*>(smraw + OFF_NUM);
    int*      sh_aim  = reinterpret_cast<int*>(smraw + OFF_AIM);

    const int tid = threadIdx.x;
    const int c   = blockIdx.x;
    const int b   = blockIdx.y;
    const int cc0 = c * 32;

    // ---- fill: gh split (r,z) packed + n ----
    for (int idx = tid; idx < 258 * 4; idx += 512) {
        int n  = idx >> 2;
        int k8 = (idx & 3) * 8;
        const uint16_t* base = &gh_all[((size_t)b * NODES + n) * G3 + cc0 + k8];
        uint4 rv = *reinterpret_cast<const uint4*>(base);
        uint4 zv = *reinterpret_cast<const uint4*>(base + 128);
        uint4 nv = *reinterpret_cast<const uint4*>(base + 256);
        uint32_t* rz = &sh_grz[n * 32 + k8];
        *reinterpret_cast<uint4*>(rz) = make_uint4(
            __byte_perm(rv.x, zv.x, 0x5410), __byte_perm(rv.x, zv.x, 0x7632),
            __byte_perm(rv.y, zv.y, 0x5410), __byte_perm(rv.y, zv.y, 0x7632));
        *reinterpret_cast<uint4*>(rz + 4) = make_uint4(
            __byte_perm(rv.z, zv.z, 0x5410), __byte_perm(rv.z, zv.z, 0x7632),
            __byte_perm(rv.w, zv.w, 0x5410), __byte_perm(rv.w, zv.w, 0x7632));
        *reinterpret_cast<uint4*>(&sh_gn[n * 32 + k8]) = nv;
    }
    // h slice + fused base copy to out
    for (int idx = tid; idx < 258 * 8; idx += 512) {
        int n = idx >> 3, jj = (idx & 7) * 4;
        float4 v = *reinterpret_cast<const float4*>(
            &node_emb[((size_t)b * NODES + n) * HDIM + cc0 + jj]);
        *reinterpret_cast<float4*>(&sh_h[n * 32 + jj]) = v;
        *reinterpret_cast<float4*>(&out[((size_t)b * NODES + n) * HDIM + cc0 + jj]) = v;
    }
    for (int idx = tid; idx < 32 * 24; idx += 512) {
        int t = idx / 24, q = idx % 24;
        int gate = q >> 3, jj = (q & 7) * 4;
        float4 v = *reinterpret_cast<const float4*>(
            &gi_ent[((size_t)b * TOPK + t) * G3 + gate * 128 + cc0 + jj]);
        *reinterpret_cast<float4*>(&sh_gi[(t * 3 + gate) * 32 + jj]) = v;
    }
    for (int idx = tid; idx < 1024; idx += 512)
        sh_acc[idx] = 0.0f;
    if (tid < 32)
        sh_num[tid] = nb_num[b * TOPK + tid];
    if (tid >= 32 && tid < 64) {
        int t = tid - 32;
        int node = aim_nodes[b * TOPK + t];
        unsigned grp = __match_any_sync(0xFFFFFFFFu, node);
        int winner = (31 - __clz(grp)) == t;
        sh_aim[t] = winner ? node : -1;
    }
    __syncthreads();

    // ---- prefix scan over num (warp 0) ----
    if (tid < 32) {
        int s = sh_num[tid];
#pragma unroll
        for (int o = 1; o < 32; o <<= 1) {
            int x = __shfl_up_sync(0xFFFFFFFFu, s, o);
            if (tid >= o) s += x;
        }
        sh_pref[tid + 1] = s;
        if (tid == 0) sh_pref[0] = 0;
    }
    __syncthreads();

    const int V = sh_pref[32];

    // ---- worklist build: packed (t | node<<5 | rel<<15) ----
    for (int idx = tid; idx < TOPK * MN; idx += 512) {
        int t = idx >> 6, m = idx & 63;
        if (m < sh_num[t]) {
            int2 nb = neighbors[(size_t)b * TOPK * MN + idx];
            sh_work[sh_pref[t] + m] = t | (nb.x << 5) | (nb.y << 15);
        }
    }
    __syncthreads();

    // ---- balanced compute ----
    const int warp = tid >> 5;
    const int lane = tid & 31;
    const int vbeg = (V * warp) >> 4;
    const int vend = (V * (warp + 1)) >> 4;

    const uint16_t* base_g = gi_rel16 + (cc0 + lane) * 4;

    int   cur_t = -1;
    float gir = 0.f, giz = 0.f, gin = 0.f, acc = 0.f;

    for (int v0 = vbeg; v0 < vend; v0 += 8) {
        const int cnt = min(8, vend - v0);
        int tt[8], nd[8]; uint2 gv[8];
#pragma unroll
        for (int j = 0; j < 8; j++) {
            if (j < cnt) {
                int w32 = sh_work[v0 + j];
                tt[j] = w32 & 31;
                nd[j] = (w32 >> 5) & 1023;
                int rel = w32 >> 15;
                gv[j] = __ldg(reinterpret_cast<const uint2*>(base_g + rel * 512));
            }
        }
#pragma unroll
        for (int j = 0; j < 8; j++) {
            if (j < cnt) {
                if (tt[j] != cur_t) {           // warp-uniform branch
                    if (cur_t >= 0) atomicAdd(&sh_acc[cur_t * 32 + lane], acc);
                    acc = 0.f;
                    cur_t = tt[j];
                    gir = sh_gi[(cur_t * 3 + 0) * 32 + lane];
                    giz = sh_gi[(cur_t * 3 + 1) * 32 + lane];
                    gin = sh_gi[(cur_t * 3 + 2) * 32 + lane];
                }
                uint32_t rz = sh_grz[nd[j] * 32 + lane];
                uint32_t gn = sh_gn[nd[j] * 32 + lane];
                const float h = sh_h[nd[j] * 32 + lane];
                float g0 = __uint_as_float(gv[j].x << 16);
                float g1 = __uint_as_float(gv[j].x & 0xFFFF0000u);
                float g2 = __uint_as_float(gv[j].y << 16);
                float ghr = __uint_as_float(rz << 16);
                float ghz = __uint_as_float(rz & 0xFFFF0000u);
                float ghn = __uint_as_float(gn << 16);
                float r = sigmoid_t(gir + g0 + ghr);
                float z = sigmoid_t(giz + g1 + ghz);
                float n = tanh_ap(fmaf(r, ghn, gin + g2));
                acc += fmaf(z, h - n, n);
            }
        }
    }
    if (cur_t >= 0) atomicAdd(&sh_acc[cur_t * 32 + lane], acc);
    __syncthreads();

    // ---- epilogue: mean + scatter winners ----
    for (int t = warp; t < TOPK; t += 16) {
        const int aim = sh_aim[t];
        if (aim >= 0) {
            const int num = sh_num[t];
            float u = (num > 0) ? sh_acc[t * 32 + lane] / (float)num : 0.f;
            out[((size_t)b * NODES + aim) * HDIM + cc0 + lane] = u;
        }
    }
}

// ---------------------------------------------------------------------------
// Host launcher
// ---------------------------------------------------------------------------
extern "C" void kernel_launch(void* const* d_in, const int* in_sizes, int n_in,
                              void* d_out, int out_size)
{
    const float* node_emb = (const float*)d_in[0];
    const float* ent_tab  = (const float*)d_in[1];
    const float* rel_tab  = (const float*)d_in[2];
    const float* W_ih     = (const float*)d_in[3];
    const float* W_hh     = (const float*)d_in[4];
    const float* b_ih     = (const float*)d_in[5];
    const float* b_hh     = (const float*)d_in[6];
    const int*   aim_nd   = (const int*)d_in[7];
    const int*   aim_ent  = (const int*)d_in[8];
    const int*   nbrs     = (const int*)d_in[9];
    const int*   nb_num   = (const int*)d_in[10];
    float* out = (float*)d_out;

    float* p_gi_ent; uint16_t *p_gi_rel, *p_gh;
    cudaGetSymbolAddress((void**)&p_gi_rel, g_gi_rel16);
    cudaGetSymbolAddress((void**)&p_gi_ent, g_gi_ent);
    cudaGetSymbolAddress((void**)&p_gh,     g_gh16);

    cudaFuncSetAttribute(gemm_mma_kernel,
        cudaFuncAttributeMaxDynamicSharedMemorySize, GEMM_SMEM);
    cudaFuncSetAttribute(aggregate_kernel,
        cudaFuncAttributeMaxDynamicSharedMemorySize, AGG_SMEM);

    // 1) fused GEMMs (bf16 tensor cores, one wave)
    gemm_mma_kernel<<<294, 256, GEMM_SMEM>>>(
        node_emb, ent_tab, rel_tab, W_ih, W_hh, b_ih, b_hh, aim_ent,
        p_gh, p_gi_ent, p_gi_rel);

    // 2) GRU + masked mean + fused base-copy/dupmask/scatter
    aggregate_kernel<<<dim3(4, BB), 512, AGG_SMEM>>>(
        node_emb, p_gi_rel, p_gi_ent, p_gh,
        (const int2*)nbrs, nb_num, aim_nd, out);
}

// round 11
// speedup vs baseline: 1.8838x; 1.4535x over previous
#include <cuda_runtime.h>
#include <cstdint>

// Problem constants
#define BB      128
#define TOPK    32
#define MN      64
#define NODES   258        // MAX_NODES + 2
#define HDIM    128
#define G3      384        // 3*H

// ---------------------------------------------------------------------------
// Device scratch
// ---------------------------------------------------------------------------
__device__ uint32_t g_gi_rel32[400 * 256];      // bf16x2 [rel][pair(64)][4]: r01,z01,n01,pad
__device__ float    g_gi_ent[BB * TOPK * G3];
__device__ uint16_t g_gh16 [BB * NODES * G3];   // gh in bf16

// ---------------------------------------------------------------------------
// Helpers
// ---------------------------------------------------------------------------
__device__ __forceinline__ float tanh_ap(float x) {
    float y; asm("tanh.approx.f32 %0, %1;" : "=f"(y) : "f"(x)); return y;
}
__device__ __forceinline__ float sigmoid_t(float x) {
    return fmaf(0.5f, tanh_ap(0.5f * x), 0.5f);
}
__device__ __forceinline__ uint32_t f2bf2(float lo, float hi) {
    uint32_t r;
    asm("cvt.rn.bf16x2.f32 %0, %1, %2;" : "=r"(r) : "f"(hi), "f"(lo));
    return r;
}
__device__ __forceinline__ uint32_t badd2(uint32_t a, uint32_t b) {
    uint32_t r; asm("add.rn.bf16x2 %0, %1, %2;" : "=r"(r) : "r"(a), "r"(b)); return r;
}
__device__ __forceinline__ uint32_t bmul2(uint32_t a, uint32_t b) {
    uint32_t r; asm("mul.rn.bf16x2 %0, %1, %2;" : "=r"(r) : "r"(a), "r"(b)); return r;
}
__device__ __forceinline__ uint32_t bfma2(uint32_t a, uint32_t b, uint32_t c) {
    uint32_t r; asm("fma.rn.bf16x2 %0, %1, %2, %3;" : "=r"(r) : "r"(a), "r"(b), "r"(c)); return r;
}
__device__ __forceinline__ uint32_t btanh2(uint32_t x) {
    uint32_t r; asm("tanh.approx.bf16x2 %0, %1;" : "=r"(r) : "r"(x)); return r;
}
#define BHALF2 0x3F003F00u
__device__ __forceinline__ float blo(uint32_t x) { return __uint_as_float(x << 16); }
__device__ __forceinline__ float bhi(uint32_t x) { return __uint_as_float(x & 0xFFFF0000u); }

__device__ __forceinline__ void mma_bf16(float* d, const uint32_t* a, const uint32_t* b) {
    asm volatile(
        "mma.sync.aligned.m16n8k16.row.col.f32.bf16.bf16.f32 "
        "{%0,%1,%2,%3}, {%4,%5,%6,%7}, {%8,%9}, {%0,%1,%2,%3};"
        : "+f"(d[0]), "+f"(d[1]), "+f"(d[2]), "+f"(d[3])
        : "r"(a[0]), "r"(a[1]), "r"(a[2]), "r"(a[3]), "r"(b[0]), "r"(b[1]));
}

// ---------------------------------------------------------------------------
// Kernel 1: fused bf16 mma.sync GEMM, 294 CTAs (one wave @ 2 CTA/SM).
// ---------------------------------------------------------------------------
#define APITCH 68
#define OFFA    0
#define OFFB    (128 * APITCH * 4)
#define OFFBIAS (OFFB + 128 * APITCH * 4)
#define OFFRIDX (OFFBIAS + 384 * 4)
#define GEMM_SMEM (OFFRIDX + 128 * 4)

__global__ __launch_bounds__(256, 2) void gemm_mma_kernel(
    const float* __restrict__ node_emb,
    const float* __restrict__ ent_tab,
    const float* __restrict__ rel_tab,
    const float* __restrict__ W_ih,
    const float* __restrict__ W_hh,
    const float* __restrict__ b_ih,
    const float* __restrict__ b_hh,
    const int*   __restrict__ aim_ent,
    uint16_t* __restrict__ out_gh,
    float* __restrict__ out_gi_ent,
    uint32_t* __restrict__ out_gi_rel)
{
    extern __shared__ char sm[];
    uint32_t* As = reinterpret_cast<uint32_t*>(sm + OFFA);
    uint32_t* Bs = reinterpret_cast<uint32_t*>(sm + OFFB);
    float*    sh_bias = reinterpret_cast<float*>(sm + OFFBIAS);
    int*      sh_ridx = reinterpret_cast<int*>(sm + OFFRIDX);

    const int tid  = threadIdx.x;
    const int wid  = tid >> 5;
    const int lane = tid & 31;

    int bx = blockIdx.x;
    const float* A; const int* gather = nullptr; int nrows;
    const float* W; int ldw, woff; const float* bias; float* outf = nullptr;
    int tile, obf = 0, orel = 0;
    if (bx < 258) {
        tile = bx;
        A = node_emb; nrows = BB * NODES;
        W = W_hh; ldw = 128; woff = 0; bias = b_hh; obf = 1;
    } else if (bx < 290) {
        tile = bx - 258;
        A = ent_tab; gather = aim_ent; nrows = BB * TOPK;
        W = W_ih; ldw = 256; woff = 0; bias = b_ih; outf = out_gi_ent;
    } else {
        tile = bx - 290;
        A = rel_tab; nrows = 400;
        W = W_ih; ldw = 256; woff = 128; bias = nullptr; orel = 1;
    }
    const int row0 = tile * 128;

    if (tid < 128) {
        int r = row0 + tid;
        sh_ridx[tid] = (r < nrows) ? (gather ? gather[r] : r) : -1;
    }
    for (int i = tid; i < G3; i += 256)
        sh_bias[i] = bias ? bias[i] : 0.0f;
    __syncthreads();

    // ---- fill A tile once (bf16 pairs) ----
    for (int idx = tid; idx < 128 * 32; idx += 256) {
        int i  = idx >> 5;
        int k4 = (idx & 31) << 2;
        int ridx = sh_ridx[i];
        float4 v = make_float4(0.f, 0.f, 0.f, 0.f);
        if (ridx >= 0)
            v = *reinterpret_cast<const float4*>(&A[(size_t)ridx * 128 + k4]);
        uint2 w = make_uint2(f2bf2(v.x, v.y), f2bf2(v.z, v.w));
        *reinterpret_cast<uint2*>(&As[i * APITCH + (k4 >> 1)]) = w;
    }

    const int quad  = lane >> 2;
    const int tq    = lane & 3;
    const int rbase = (wid >> 2) * 64;
    const int cbase = (wid & 3) * 32;

    for (int gate = 0; gate < 3; gate++) {
        for (int idx = tid; idx < 128 * 32; idx += 256) {
            int n  = idx >> 5;
            int k4 = (idx & 31) << 2;
            float4 v = *reinterpret_cast<const float4*>(
                &W[(size_t)(gate * 128 + n) * ldw + woff + k4]);
            uint2 w = make_uint2(f2bf2(v.x, v.y), f2bf2(v.z, v.w));
            *reinterpret_cast<uint2*>(&Bs[n * APITCH + (k4 >> 1)]) = w;
        }
        __syncthreads();

        float acc[4][4][4];
#pragma unroll
        for (int mt = 0; mt < 4; mt++)
#pragma unroll
            for (int nt = 0; nt < 4; nt++)
#pragma unroll
                for (int r = 0; r < 4; r++) acc[mt][nt][r] = 0.f;

#pragma unroll
        for (int ks = 0; ks < 8; ks++) {
            const int k0 = ks * 8;
            uint32_t af[4][4];
#pragma unroll
            for (int mt = 0; mt < 4; mt++) {
                int r = rbase + mt * 16 + quad;
                af[mt][0] = As[r * APITCH + k0 + tq];
                af[mt][1] = As[(r + 8) * APITCH + k0 + tq];
                af[mt][2] = As[r * APITCH + k0 + tq + 4];
                af[mt][3] = As[(r + 8) * APITCH + k0 + tq + 4];
            }
            uint32_t bf[4][2];
#pragma unroll
            for (int nt = 0; nt < 4; nt++) {
                int c = cbase + nt * 8 + quad;
                bf[nt][0] = Bs[c * APITCH + k0 + tq];
                bf[nt][1] = Bs[c * APITCH + k0 + tq + 4];
            }
#pragma unroll
            for (int mt = 0; mt < 4; mt++)
#pragma unroll
                for (int nt = 0; nt < 4; nt++)
                    mma_bf16(acc[mt][nt], af[mt], bf[nt]);
        }

#pragma unroll
        for (int mt = 0; mt < 4; mt++) {
#pragma unroll
            for (int nt = 0; nt < 4; nt++) {
                const int col = cbase + nt * 8 + tq * 2;
                const float b0 = sh_bias[gate * 128 + col];
                const float b1 = sh_bias[gate * 128 + col + 1];
                const int r1 = row0 + rbase + mt * 16 + quad;
                const int r2 = r1 + 8;
                if (obf) {
                    if (r1 < nrows)
                        *reinterpret_cast<uint32_t*>(
                            &out_gh[(size_t)r1 * G3 + gate * 128 + col]) =
                            f2bf2(acc[mt][nt][0] + b0, acc[mt][nt][1] + b1);
                    if (r2 < nrows)
                        *reinterpret_cast<uint32_t*>(
                            &out_gh[(size_t)r2 * G3 + gate * 128 + col]) =
                            f2bf2(acc[mt][nt][2] + b0, acc[mt][nt][3] + b1);
                } else if (orel) {
                    // bf16x2 pair-interleaved: [rel][pair][4] slots r,z,n,pad
                    if (r1 < nrows)
                        out_gi_rel[(size_t)r1 * 256 + (col >> 1) * 4 + gate] =
                            f2bf2(acc[mt][nt][0] + b0, acc[mt][nt][1] + b1);
                    if (r2 < nrows)
                        out_gi_rel[(size_t)r2 * 256 + (col >> 1) * 4 + gate] =
                            f2bf2(acc[mt][nt][2] + b0, acc[mt][nt][3] + b1);
                } else {
                    if (r1 < nrows)
                        *reinterpret_cast<float2*>(&outf[(size_t)r1 * G3 + gate * 128 + col]) =
                            make_float2(acc[mt][nt][0] + b0, acc[mt][nt][1] + b1);
                    if (r2 < nrows)
                        *reinterpret_cast<float2*>(&outf[(size_t)r2 * G3 + gate * 128 + col]) =
                            make_float2(acc[mt][nt][2] + b0, acc[mt][nt][3] + b1);
                }
            }
        }
        __syncthreads();
    }
}

// ---------------------------------------------------------------------------
// Kernel 2: GRU aggregation, bf16x2 SIMD over channel pairs.
// CTA = (batch, 64-ch chunk); 1024 threads; lane owns a channel pair.
// ---------------------------------------------------------------------------
#define OFF_GR   0                               // u32 [258*32] = 33024
#define OFF_GZ   33024
#define OFF_GN   66048
#define OFF_H    99072                           // bf16x2 [258*32] = 33024
#define OFF_GIR  132096                          // u32 [32*32] = 4096
#define OFF_GIZ  136192
#define OFF_GIN  140288
#define OFF_WORK 144384                          // i32 [2048] = 8192
#define OFF_ACC  152576                          // f32 [32*64] = 8192
#define OFF_PREF 160768                          // i32 [33] pad 144
#define OFF_NUM  160912
#define OFF_AIM  161040
#define AGG_SMEM 161168

__global__ __launch_bounds__(1024, 1) void aggregate_kernel(
    const float*    __restrict__ node_emb,
    const uint32_t* __restrict__ gi_rel32,
    const float*    __restrict__ gi_ent,
    const uint16_t* __restrict__ gh_all,
    const int2*     __restrict__ neighbors,
    const int*      __restrict__ nb_num,
    const int*      __restrict__ aim_nodes,
    float* __restrict__ out)
{
    extern __shared__ char smraw[];
    uint32_t* sh_gr   = reinterpret_cast<uint32_t*>(smraw + OFF_GR);
    uint32_t* sh_gz   = reinterpret_cast<uint32_t*>(smraw + OFF_GZ);
    uint32_t* sh_gn   = reinterpret_cast<uint32_t*>(smraw + OFF_GN);
    uint32_t* sh_h    = reinterpret_cast<uint32_t*>(smraw + OFF_H);
    uint32_t* sh_gir  = reinterpret_cast<uint32_t*>(smraw + OFF_GIR);
    uint32_t* sh_giz  = reinterpret_cast<uint32_t*>(smraw + OFF_GIZ);
    uint32_t* sh_gin  = reinterpret_cast<uint32_t*>(smraw + OFF_GIN);
    int*      sh_work = reinterpret_cast<int*>(smraw + OFF_WORK);
    float*    sh_acc  = reinterpret_cast<float*>(smraw + OFF_ACC);
    int*      sh_pref = reinterpret_cast<int*>(smraw + OFF_PREF);
    int*      sh_num  = reinterpret_cast<int*>(smraw + OFF_NUM);
    int*      sh_aim  = reinterpret_cast<int*>(smraw + OFF_AIM);

    const int tid = threadIdx.x;
    const int c   = blockIdx.x;        // 64-channel chunk (0..1)
    const int b   = blockIdx.y;
    const int cc0 = c * 64;

    // ---- fill gh gates: uint4 = 4 pairs per load ----
    for (int idx = tid; idx < 258 * 24; idx += 1024) {
        int n = idx / 24, q = idx % 24;
        int gate = q >> 3, u = q & 7;
        uint4 v = *reinterpret_cast<const uint4*>(
            &gh_all[((size_t)b * NODES + n) * G3 + gate * 128 + cc0 + u * 8]);
        uint32_t* dst = (gate == 0 ? sh_gr : gate == 1 ? sh_gz : sh_gn);
        *reinterpret_cast<uint4*>(&dst[n * 32 + u * 4]) = v;
    }
    // ---- h slice (bf16x2) + fused base copy ----
    for (int idx = tid; idx < 258 * 16; idx += 1024) {
        int n = idx >> 4, q = idx & 15;
        float4 v = *reinterpret_cast<const float4*>(
            &node_emb[((size_t)b * NODES + n) * HDIM + cc0 + q * 4]);
        *reinterpret_cast<float4*>(&out[((size_t)b * NODES + n) * HDIM + cc0 + q * 4]) = v;
        uint2 w = make_uint2(f2bf2(v.x, v.y), f2bf2(v.z, v.w));
        *reinterpret_cast<uint2*>(&sh_h[n * 32 + q * 2]) = w;
    }
    // ---- gi_ent packed bf16x2 per pair ----
    for (int idx = tid; idx < 32 * 96; idx += 1024) {
        int t = idx / 96, q = idx % 96;
        int gate = q >> 5, p = q & 31;
        float2 v = *reinterpret_cast<const float2*>(
            &gi_ent[((size_t)b * TOPK + t) * G3 + gate * 128 + cc0 + 2 * p]);
        uint32_t* dst = (gate == 0 ? sh_gir : gate == 1 ? sh_giz : sh_gin);
        dst[t * 32 + p] = f2bf2(v.x, v.y);
    }
    for (int idx = tid; idx < 2048; idx += 1024)
        sh_acc[idx] = 0.0f;
    if (tid < 32)
        sh_num[tid] = nb_num[b * TOPK + tid];
    if (tid >= 32 && tid < 64) {
        int t = tid - 32;
        int node = aim_nodes[b * TOPK + t];
        unsigned grp = __match_any_sync(0xFFFFFFFFu, node);
        int winner = (31 - __clz(grp)) == t;
        sh_aim[t] = winner ? node : -1;
    }
    __syncthreads();

    // ---- prefix scan over num (warp 0) ----
    if (tid < 32) {
        int s = sh_num[tid];
#pragma unroll
        for (int o = 1; o < 32; o <<= 1) {
            int x = __shfl_up_sync(0xFFFFFFFFu, s, o);
            if (tid >= o) s += x;
        }
        sh_pref[tid + 1] = s;
        if (tid == 0) sh_pref[0] = 0;
    }
    __syncthreads();

    const int V = sh_pref[32];

    // ---- worklist build ----
    for (int idx = tid; idx < TOPK * MN; idx += 1024) {
        int t = idx >> 6, m = idx & 63;
        if (m < sh_num[t]) {
            int2 nb = neighbors[(size_t)b * TOPK * MN + idx];
            sh_work[sh_pref[t] + m] = t | (nb.x << 5) | (nb.y << 15);
        }
    }
    __syncthreads();

    // ---- balanced compute: 32 warps ----
    const int warp = tid >> 5;
    const int lane = tid & 31;
    const int vbeg = (V * warp) >> 5;
    const int vend = (V * (warp + 1)) >> 5;

    const uint32_t* base_g = gi_rel32 + (c * 32 + lane) * 4;

    int   cur_t = -1;
    uint32_t gir = 0, giz = 0, gin = 0;
    float acc0 = 0.f, acc1 = 0.f;

    for (int v0 = vbeg; v0 < vend; v0 += 4) {
        const int cnt = min(4, vend - v0);
        int w[4]; uint4 gv[4];
#pragma unroll
        for (int j = 0; j < 4; j++) {
            if (j < cnt) {
                w[j] = sh_work[v0 + j];
                int rel = w[j] >> 15;
                gv[j] = __ldg(reinterpret_cast<const uint4*>(base_g + rel * 256));
            }
        }
#pragma unroll
        for (int j = 0; j < 4; j++) {
            if (j < cnt) {
                int t = w[j] & 31;
                if (t != cur_t) {               // warp-uniform
                    if (cur_t >= 0) {
                        atomicAdd(&sh_acc[cur_t * 64 + 2 * lane],     acc0);
                        atomicAdd(&sh_acc[cur_t * 64 + 2 * lane + 1], acc1);
                    }
                    acc0 = acc1 = 0.f;
                    cur_t = t;
                    gir = sh_gir[t * 32 + lane];
                    giz = sh_giz[t * 32 + lane];
                    gin = sh_gin[t * 32 + lane];
                }
                int nd = (w[j] >> 5) & 1023;
                uint32_t gr = sh_gr[nd * 32 + lane];
                uint32_t gz = sh_gz[nd * 32 + lane];
                uint32_t gn = sh_gn[nd * 32 + lane];
                uint32_t hh = sh_h[nd * 32 + lane];
                // r gate: fully packed bf16
                uint32_t pre_r = badd2(badd2(gir, gv[j].x), gr);
                uint32_t r = bfma2(btanh2(bmul2(pre_r, BHALF2)), BHALF2, BHALF2);
                // z, n: packed preactivation, fp32 transcendental
                uint32_t pre_z = badd2(badd2(giz, gv[j].y), gz);
                uint32_t pre_n = bfma2(r, gn, badd2(gin, gv[j].z));
                float z0 = sigmoid_t(blo(pre_z)), z1 = sigmoid_t(bhi(pre_z));
                float n0 = tanh_ap(blo(pre_n)),   n1 = tanh_ap(bhi(pre_n));
                float h0 = blo(hh), h1 = bhi(hh);
                acc0 += fmaf(z0, h0 - n0, n0);
                acc1 += fmaf(z1, h1 - n1, n1);
            }
        }
    }
    if (cur_t >= 0) {
        atomicAdd(&sh_acc[cur_t * 64 + 2 * lane],     acc0);
        atomicAdd(&sh_acc[cur_t * 64 + 2 * lane + 1], acc1);
    }
    __syncthreads();

    // ---- epilogue: mean + scatter winners (warp t) ----
    {
        const int t = warp;
        const int aim = sh_aim[t];
        if (aim >= 0) {
            const int num = sh_num[t];
            float inv = (num > 0) ? 1.0f / (float)num : 0.f;
            float2 u = make_float2(sh_acc[t * 64 + 2 * lane] * inv,
                                   sh_acc[t * 64 + 2 * lane + 1] * inv);
            *reinterpret_cast<float2*>(
                &out[((size_t)b * NODES + aim) * HDIM + cc0 + 2 * lane]) = u;
        }
    }
}

// ---------------------------------------------------------------------------
// Host launcher
// ---------------------------------------------------------------------------
extern "C" void kernel_launch(void* const* d_in, const int* in_sizes, int n_in,
                              void* d_out, int out_size)
{
    const float* node_emb = (const float*)d_in[0];
    const float* ent_tab  = (const float*)d_in[1];
    const float* rel_tab  = (const float*)d_in[2];
    const float* W_ih     = (const float*)d_in[3];
    const float* W_hh     = (const float*)d_in[4];
    const float* b_ih     = (const float*)d_in[5];
    const float* b_hh     = (const float*)d_in[6];
    const int*   aim_nd   = (const int*)d_in[7];
    const int*   aim_ent  = (const int*)d_in[8];
    const int*   nbrs     = (const int*)d_in[9];
    const int*   nb_num   = (const int*)d_in[10];
    float* out = (float*)d_out;

    float* p_gi_ent; uint32_t* p_gi_rel; uint16_t* p_gh;
    cudaGetSymbolAddress((void**)&p_gi_rel, g_gi_rel32);
    cudaGetSymbolAddress((void**)&p_gi_ent, g_gi_ent);
    cudaGetSymbolAddress((void**)&p_gh,     g_gh16);

    cudaFuncSetAttribute(gemm_mma_kernel,
        cudaFuncAttributeMaxDynamicSharedMemorySize, GEMM_SMEM);
    cudaFuncSetAttribute(aggregate_kernel,
        cudaFuncAttributeMaxDynamicSharedMemorySize, AGG_SMEM);

    // 1) fused GEMMs (bf16 tensor cores, one wave)
    gemm_mma_kernel<<<294, 256, GEMM_SMEM>>>(
        node_emb, ent_tab, rel_tab, W_ih, W_hh, b_ih, b_hh, aim_ent,
        p_gh, p_gi_ent, p_gi_rel);

    // 2) GRU aggregation, bf16x2 channel pairs (2 chunks x 128 batches)
    aggregate_kernel<<<dim3(2, BB), 1024, AGG_SMEM>>>(
        node_emb, p_gi_rel, p_gi_ent, p_gh,
        (const int2*)nbrs, nb_num, aim_nd, out);
}

// round 12
// speedup vs baseline: 1.8857x; 1.0010x over previous
#include <cuda_runtime.h>
#include <cstdint>

// Problem constants
#define BB      128
#define TOPK    32
#define MN      64
#define NODES   258        // MAX_NODES + 2
#define HDIM    128
#define G3      384        // 3*H

// ---------------------------------------------------------------------------
// Device scratch
// ---------------------------------------------------------------------------
__device__ uint32_t g_gi_rel32[400 * 256];      // bf16x2 [rel][pair(64)][4]: r01,z01,n01,pad
__device__ float    g_gi_ent[BB * TOPK * G3];
__device__ uint16_t g_gh16 [BB * NODES * G3];   // gh in bf16

// ---------------------------------------------------------------------------
// Helpers
// ---------------------------------------------------------------------------
__device__ __forceinline__ uint32_t f2bf2(float lo, float hi) {
    uint32_t r;
    asm("cvt.rn.bf16x2.f32 %0, %1, %2;" : "=r"(r) : "f"(hi), "f"(lo));
    return r;
}
__device__ __forceinline__ uint32_t badd2(uint32_t a, uint32_t b) {
    uint32_t r; asm("add.rn.bf16x2 %0, %1, %2;" : "=r"(r) : "r"(a), "r"(b)); return r;
}
__device__ __forceinline__ uint32_t bsub2(uint32_t a, uint32_t b) {
    uint32_t r; asm("sub.rn.bf16x2 %0, %1, %2;" : "=r"(r) : "r"(a), "r"(b)); return r;
}
__device__ __forceinline__ uint32_t bmul2(uint32_t a, uint32_t b) {
    uint32_t r; asm("mul.rn.bf16x2 %0, %1, %2;" : "=r"(r) : "r"(a), "r"(b)); return r;
}
__device__ __forceinline__ uint32_t bfma2(uint32_t a, uint32_t b, uint32_t c) {
    uint32_t r; asm("fma.rn.bf16x2 %0, %1, %2, %3;" : "=r"(r) : "r"(a), "r"(b), "r"(c)); return r;
}
__device__ __forceinline__ uint32_t btanh2(uint32_t x) {
    uint32_t r; asm("tanh.approx.bf16x2 %0, %1;" : "=r"(r) : "r"(x)); return r;
}
#define BHALF2 0x3F003F00u
__device__ __forceinline__ float blo(uint32_t x) { return __uint_as_float(x << 16); }
__device__ __forceinline__ float bhi(uint32_t x) { return __uint_as_float(x & 0xFFFF0000u); }

__device__ __forceinline__ void mma_bf16(float* d, const uint32_t* a, const uint32_t* b) {
    asm volatile(
        "mma.sync.aligned.m16n8k16.row.col.f32.bf16.bf16.f32 "
        "{%0,%1,%2,%3}, {%4,%5,%6,%7}, {%8,%9}, {%0,%1,%2,%3};"
        : "+f"(d[0]), "+f"(d[1]), "+f"(d[2]), "+f"(d[3])
        : "r"(a[0]), "r"(a[1]), "r"(a[2]), "r"(a[3]), "r"(b[0]), "r"(b[1]));
}

// ---------------------------------------------------------------------------
// Kernel 1: fused bf16 mma.sync GEMM, 294 CTAs (one wave @ 2 CTA/SM).
// ---------------------------------------------------------------------------
#define APITCH 68
#define OFFA    0
#define OFFB    (128 * APITCH * 4)
#define OFFBIAS (OFFB + 128 * APITCH * 4)
#define OFFRIDX (OFFBIAS + 384 * 4)
#define GEMM_SMEM (OFFRIDX + 128 * 4)

__global__ __launch_bounds__(256, 2) void gemm_mma_kernel(
    const float* __restrict__ node_emb,
    const float* __restrict__ ent_tab,
    const float* __restrict__ rel_tab,
    const float* __restrict__ W_ih,
    const float* __restrict__ W_hh,
    const float* __restrict__ b_ih,
    const float* __restrict__ b_hh,
    const int*   __restrict__ aim_ent,
    uint16_t* __restrict__ out_gh,
    float* __restrict__ out_gi_ent,
    uint32_t* __restrict__ out_gi_rel)
{
    extern __shared__ char sm[];
    uint32_t* As = reinterpret_cast<uint32_t*>(sm + OFFA);
    uint32_t* Bs = reinterpret_cast<uint32_t*>(sm + OFFB);
    float*    sh_bias = reinterpret_cast<float*>(sm + OFFBIAS);
    int*      sh_ridx = reinterpret_cast<int*>(sm + OFFRIDX);

    const int tid  = threadIdx.x;
    const int wid  = tid >> 5;
    const int lane = tid & 31;

    int bx = blockIdx.x;
    const float* A; const int* gather = nullptr; int nrows;
    const float* W; int ldw, woff; const float* bias; float* outf = nullptr;
    int tile, obf = 0, orel = 0;
    if (bx < 258) {
        tile = bx;
        A = node_emb; nrows = BB * NODES;
        W = W_hh; ldw = 128; woff = 0; bias = b_hh; obf = 1;
    } else if (bx < 290) {
        tile = bx - 258;
        A = ent_tab; gather = aim_ent; nrows = BB * TOPK;
        W = W_ih; ldw = 256; woff = 0; bias = b_ih; outf = out_gi_ent;
    } else {
        tile = bx - 290;
        A = rel_tab; nrows = 400;
        W = W_ih; ldw = 256; woff = 128; bias = nullptr; orel = 1;
    }
    const int row0 = tile * 128;

    if (tid < 128) {
        int r = row0 + tid;
        sh_ridx[tid] = (r < nrows) ? (gather ? gather[r] : r) : -1;
    }
    for (int i = tid; i < G3; i += 256)
        sh_bias[i] = bias ? bias[i] : 0.0f;
    __syncthreads();

    // ---- fill A tile once (bf16 pairs) ----
    for (int idx = tid; idx < 128 * 32; idx += 256) {
        int i  = idx >> 5;
        int k4 = (idx & 31) << 2;
        int ridx = sh_ridx[i];
        float4 v = make_float4(0.f, 0.f, 0.f, 0.f);
        if (ridx >= 0)
            v = *reinterpret_cast<const float4*>(&A[(size_t)ridx * 128 + k4]);
        uint2 w = make_uint2(f2bf2(v.x, v.y), f2bf2(v.z, v.w));
        *reinterpret_cast<uint2*>(&As[i * APITCH + (k4 >> 1)]) = w;
    }

    const int quad  = lane >> 2;
    const int tq    = lane & 3;
    const int rbase = (wid >> 2) * 64;
    const int cbase = (wid & 3) * 32;

    for (int gate = 0; gate < 3; gate++) {
        for (int idx = tid; idx < 128 * 32; idx += 256) {
            int n  = idx >> 5;
            int k4 = (idx & 31) << 2;
            float4 v = *reinterpret_cast<const float4*>(
                &W[(size_t)(gate * 128 + n) * ldw + woff + k4]);
            uint2 w = make_uint2(f2bf2(v.x, v.y), f2bf2(v.z, v.w));
            *reinterpret_cast<uint2*>(&Bs[n * APITCH + (k4 >> 1)]) = w;
        }
        __syncthreads();

        float acc[4][4][4];
#pragma unroll
        for (int mt = 0; mt < 4; mt++)
#pragma unroll
            for (int nt = 0; nt < 4; nt++)
#pragma unroll
                for (int r = 0; r < 4; r++) acc[mt][nt][r] = 0.f;

#pragma unroll
        for (int ks = 0; ks < 8; ks++) {
            const int k0 = ks * 8;
            uint32_t af[4][4];
#pragma unroll
            for (int mt = 0; mt < 4; mt++) {
                int r = rbase + mt * 16 + quad;
                af[mt][0] = As[r * APITCH + k0 + tq];
                af[mt][1] = As[(r + 8) * APITCH + k0 + tq];
                af[mt][2] = As[r * APITCH + k0 + tq + 4];
                af[mt][3] = As[(r + 8) * APITCH + k0 + tq + 4];
            }
            uint32_t bf[4][2];
#pragma unroll
            for (int nt = 0; nt < 4; nt++) {
                int c = cbase + nt * 8 + quad;
                bf[nt][0] = Bs[c * APITCH + k0 + tq];
                bf[nt][1] = Bs[c * APITCH + k0 + tq + 4];
            }
#pragma unroll
            for (int mt = 0; mt < 4; mt++)
#pragma unroll
                for (int nt = 0; nt < 4; nt++)
                    mma_bf16(acc[mt][nt], af[mt], bf[nt]);
        }

#pragma unroll
        for (int mt = 0; mt < 4; mt++) {
#pragma unroll
            for (int nt = 0; nt < 4; nt++) {
                const int col = cbase + nt * 8 + tq * 2;
                const float b0 = sh_bias[gate * 128 + col];
                const float b1 = sh_bias[gate * 128 + col + 1];
                const int r1 = row0 + rbase + mt * 16 + quad;
                const int r2 = r1 + 8;
                if (obf) {
                    if (r1 < nrows)
                        *reinterpret_cast<uint32_t*>(
                            &out_gh[(size_t)r1 * G3 + gate * 128 + col]) =
                            f2bf2(acc[mt][nt][0] + b0, acc[mt][nt][1] + b1);
                    if (r2 < nrows)
                        *reinterpret_cast<uint32_t*>(
                            &out_gh[(size_t)r2 * G3 + gate * 128 + col]) =
                            f2bf2(acc[mt][nt][2] + b0, acc[mt][nt][3] + b1);
                } else if (orel) {
                    if (r1 < nrows)
                        out_gi_rel[(size_t)r1 * 256 + (col >> 1) * 4 + gate] =
                            f2bf2(acc[mt][nt][0] + b0, acc[mt][nt][1] + b1);
                    if (r2 < nrows)
                        out_gi_rel[(size_t)r2 * 256 + (col >> 1) * 4 + gate] =
                            f2bf2(acc[mt][nt][2] + b0, acc[mt][nt][3] + b1);
                } else {
                    if (r1 < nrows)
                        *reinterpret_cast<float2*>(&outf[(size_t)r1 * G3 + gate * 128 + col]) =
                            make_float2(acc[mt][nt][0] + b0, acc[mt][nt][1] + b1);
                    if (r2 < nrows)
                        *reinterpret_cast<float2*>(&outf[(size_t)r2 * G3 + gate * 128 + col]) =
                            make_float2(acc[mt][nt][2] + b0, acc[mt][nt][3] + b1);
                }
            }
        }
        __syncthreads();
    }
}

// ---------------------------------------------------------------------------
// Kernel 2: GRU aggregation, fully packed bf16x2 gates.
// CTA = (batch, 64-ch chunk); 1024 threads; lane owns a channel pair.
// ---------------------------------------------------------------------------
#define OFF_GR   0                               // u32 [258*32] = 33024
#define OFF_GZ   33024
#define OFF_GN   66048
#define OFF_H    99072                           // bf16x2 [258*32] = 33024
#define OFF_GIR  132096                          // u32 [32*32] = 4096
#define OFF_GIZ  136192
#define OFF_GIN  140288
#define OFF_WORK 144384                          // i32 [2048] = 8192
#define OFF_ACC  152576                          // f32 [32*64] = 8192
#define OFF_PREF 160768                          // i32 [33] pad 144
#define OFF_NUM  160912
#define OFF_AIM  161040
#define AGG_SMEM 161168

__global__ __launch_bounds__(1024, 1) void aggregate_kernel(
    const float*    __restrict__ node_emb,
    const uint32_t* __restrict__ gi_rel32,
    const float*    __restrict__ gi_ent,
    const uint16_t* __restrict__ gh_all,
    const int2*     __restrict__ neighbors,
    const int*      __restrict__ nb_num,
    const int*      __restrict__ aim_nodes,
    float* __restrict__ out)
{
    extern __shared__ char smraw[];
    uint32_t* sh_gr   = reinterpret_cast<uint32_t*>(smraw + OFF_GR);
    uint32_t* sh_gz   = reinterpret_cast<uint32_t*>(smraw + OFF_GZ);
    uint32_t* sh_gn   = reinterpret_cast<uint32_t*>(smraw + OFF_GN);
    uint32_t* sh_h    = reinterpret_cast<uint32_t*>(smraw + OFF_H);
    uint32_t* sh_gir  = reinterpret_cast<uint32_t*>(smraw + OFF_GIR);
    uint32_t* sh_giz  = reinterpret_cast<uint32_t*>(smraw + OFF_GIZ);
    uint32_t* sh_gin  = reinterpret_cast<uint32_t*>(smraw + OFF_GIN);
    int*      sh_work = reinterpret_cast<int*>(smraw + OFF_WORK);
    float*    sh_acc  = reinterpret_cast<float*>(smraw + OFF_ACC);
    int*      sh_pref = reinterpret_cast<int*>(smraw + OFF_PREF);
    int*      sh_num  = reinterpret_cast<int*>(smraw + OFF_NUM);
    int*      sh_aim  = reinterpret_cast<int*>(smraw + OFF_AIM);

    const int tid = threadIdx.x;
    const int c   = blockIdx.x;        // 64-channel chunk (0..1)
    const int b   = blockIdx.y;
    const int cc0 = c * 64;

    // ---- fill gh gates ----
    for (int idx = tid; idx < 258 * 24; idx += 1024) {
        int n = idx / 24, q = idx % 24;
        int gate = q >> 3, u = q & 7;
        uint4 v = *reinterpret_cast<const uint4*>(
            &gh_all[((size_t)b * NODES + n) * G3 + gate * 128 + cc0 + u * 8]);
        uint32_t* dst = (gate == 0 ? sh_gr : gate == 1 ? sh_gz : sh_gn);
        *reinterpret_cast<uint4*>(&dst[n * 32 + u * 4]) = v;
    }
    // ---- h slice (bf16x2) + fused base copy ----
    for (int idx = tid; idx < 258 * 16; idx += 1024) {
        int n = idx >> 4, q = idx & 15;
        float4 v = *reinterpret_cast<const float4*>(
            &node_emb[((size_t)b * NODES + n) * HDIM + cc0 + q * 4]);
        *reinterpret_cast<float4*>(&out[((size_t)b * NODES + n) * HDIM + cc0 + q * 4]) = v;
        uint2 w = make_uint2(f2bf2(v.x, v.y), f2bf2(v.z, v.w));
        *reinterpret_cast<uint2*>(&sh_h[n * 32 + q * 2]) = w;
    }
    // ---- gi_ent packed bf16x2 per pair ----
    for (int idx = tid; idx < 32 * 96; idx += 1024) {
        int t = idx / 96, q = idx % 96;
        int gate = q >> 5, p = q & 31;
        float2 v = *reinterpret_cast<const float2*>(
            &gi_ent[((size_t)b * TOPK + t) * G3 + gate * 128 + cc0 + 2 * p]);
        uint32_t* dst = (gate == 0 ? sh_gir : gate == 1 ? sh_giz : sh_gin);
        dst[t * 32 + p] = f2bf2(v.x, v.y);
    }
    for (int idx = tid; idx < 2048; idx += 1024)
        sh_acc[idx] = 0.0f;
    if (tid < 32)
        sh_num[tid] = nb_num[b * TOPK + tid];
    if (tid >= 32 && tid < 64) {
        int t = tid - 32;
        int node = aim_nodes[b * TOPK + t];
        unsigned grp = __match_any_sync(0xFFFFFFFFu, node);
        int winner = (31 - __clz(grp)) == t;
        sh_aim[t] = winner ? node : -1;
    }
    __syncthreads();

    // ---- prefix scan over num (warp 0) ----
    if (tid < 32) {
        int s = sh_num[tid];
#pragma unroll
        for (int o = 1; o < 32; o <<= 1) {
            int x = __shfl_up_sync(0xFFFFFFFFu, s, o);
            if (tid >= o) s += x;
        }
        sh_pref[tid + 1] = s;
        if (tid == 0) sh_pref[0] = 0;
    }
    __syncthreads();

    const int V = sh_pref[32];

    // ---- worklist build ----
    for (int idx = tid; idx < TOPK * MN; idx += 1024) {
        int t = idx >> 6, m = idx & 63;
        if (m < sh_num[t]) {
            int2 nb = neighbors[(size_t)b * TOPK * MN + idx];
            sh_work[sh_pref[t] + m] = t | (nb.x << 5) | (nb.y << 15);
        }
    }
    __syncthreads();

    // ---- balanced compute: 32 warps ----
    const int warp = tid >> 5;
    const int lane = tid & 31;
    const int vbeg = (V * warp) >> 5;
    const int vend = (V * (warp + 1)) >> 5;

    const uint32_t* base_g = gi_rel32 + (c * 32 + lane) * 4;

    int   cur_t = -1;
    uint32_t gir = 0, giz = 0, gin = 0;
    float acc0 = 0.f, acc1 = 0.f;

    for (int v0 = vbeg; v0 < vend; v0 += 4) {
        const int cnt = min(4, vend - v0);
        int w[4]; uint4 gv[4];
#pragma unroll
        for (int j = 0; j < 4; j++) {
            if (j < cnt) {
                w[j] = sh_work[v0 + j];
                int rel = w[j] >> 15;
                gv[j] = __ldg(reinterpret_cast<const uint4*>(base_g + rel * 256));
            }
        }
#pragma unroll
        for (int j = 0; j < 4; j++) {
            if (j < cnt) {
                int t = w[j] & 31;
                if (t != cur_t) {               // warp-uniform
                    if (cur_t >= 0) {
                        atomicAdd(&sh_acc[cur_t * 64 + 2 * lane],     acc0);
                        atomicAdd(&sh_acc[cur_t * 64 + 2 * lane + 1], acc1);
                    }
                    acc0 = acc1 = 0.f;
                    cur_t = t;
                    gir = sh_gir[t * 32 + lane];
                    giz = sh_giz[t * 32 + lane];
                    gin = sh_gin[t * 32 + lane];
                }
                int nd = (w[j] >> 5) & 1023;
                uint32_t gr = sh_gr[nd * 32 + lane];
                uint32_t gz = sh_gz[nd * 32 + lane];
                uint32_t gn = sh_gn[nd * 32 + lane];
                uint32_t hh = sh_h[nd * 32 + lane];
                // r gate (packed sigmoid)
                uint32_t pre_r = badd2(badd2(gir, gv[j].x), gr);
                uint32_t r = bfma2(btanh2(bmul2(pre_r, BHALF2)), BHALF2, BHALF2);
                // z gate (packed sigmoid)
                uint32_t pre_z = badd2(badd2(giz, gv[j].y), gz);
                uint32_t z = bfma2(btanh2(bmul2(pre_z, BHALF2)), BHALF2, BHALF2);
                // n gate (packed tanh)
                uint32_t pre_n = bfma2(r, gn, badd2(gin, gv[j].z));
                uint32_t n = btanh2(pre_n);
                // h_new = z*(h-n) + n  (packed), accumulate fp32
                uint32_t hn = bfma2(z, bsub2(hh, n), n);
                acc0 += blo(hn);
                acc1 += bhi(hn);
            }
        }
    }
    if (cur_t >= 0) {
        atomicAdd(&sh_acc[cur_t * 64 + 2 * lane],     acc0);
        atomicAdd(&sh_acc[cur_t * 64 + 2 * lane + 1], acc1);
    }
    __syncthreads();

    // ---- epilogue: mean + scatter winners (warp t) ----
    {
        const int t = warp;
        const int aim = sh_aim[t];
        if (aim >= 0) {
            const int num = sh_num[t];
            float inv = (num > 0) ? 1.0f / (float)num : 0.f;
            float2 u = make_float2(sh_acc[t * 64 + 2 * lane] * inv,
                                   sh_acc[t * 64 + 2 * lane + 1] * inv);
            *reinterpret_cast<float2*>(
                &out[((size_t)b * NODES + aim) * HDIM + cc0 + 2 * lane]) = u;
        }
    }
}

// ---------------------------------------------------------------------------
// Host launcher
// ---------------------------------------------------------------------------
extern "C" void kernel_launch(void* const* d_in, const int* in_sizes, int n_in,
                              void* d_out, int out_size)
{
    const float* node_emb = (const float*)d_in[0];
    const float* ent_tab  = (const float*)d_in[1];
    const float* rel_tab  = (const float*)d_in[2];
    const float* W_ih     = (const float*)d_in[3];
    const float* W_hh     = (const float*)d_in[4];
    const float* b_ih     = (const float*)d_in[5];
    const float* b_hh     = (const float*)d_in[6];
    const int*   aim_nd   = (const int*)d_in[7];
    const int*   aim_ent  = (const int*)d_in[8];
    const int*   nbrs     = (const int*)d_in[9];
    const int*   nb_num   = (const int*)d_in[10];
    float* out = (float*)d_out;

    float* p_gi_ent; uint32_t* p_gi_rel; uint16_t* p_gh;
    cudaGetSymbolAddress((void**)&p_gi_rel, g_gi_rel32);
    cudaGetSymbolAddress((void**)&p_gi_ent, g_gi_ent);
    cudaGetSymbolAddress((void**)&p_gh,     g_gh16);

    cudaFuncSetAttribute(gemm_mma_kernel,
        cudaFuncAttributeMaxDynamicSharedMemorySize, GEMM_SMEM);
    cudaFuncSetAttribute(aggregate_kernel,
        cudaFuncAttributeMaxDynamicSharedMemorySize, AGG_SMEM);

    // 1) fused GEMMs (bf16 tensor cores, one wave)
    gemm_mma_kernel<<<294, 256, GEMM_SMEM>>>(
        node_emb, ent_tab, rel_tab, W_ih, W_hh, b_ih, b_hh, aim_ent,
        p_gh, p_gi_ent, p_gi_rel);

    // 2) GRU aggregation, fully packed bf16x2
    aggregate_kernel<<<dim3(2, BB), 1024, AGG_SMEM>>>(
        node_emb, p_gi_rel, p_gi_ent, p_gh,
        (const int2*)nbrs, nb_num, aim_nd, out);
}